// round 11
// baseline (speedup 1.0000x reference)
#include <cuda_runtime.h>
#include <cuda_fp16.h>
#include <cstdint>
#include <math.h>

// Problem dims
#define BB 32
#define VV 48
#define II 24
#define HH 768

#define M_ENC (BB*VV)        // 1536
#define M_HA  (BB*II)        // 768
#define M_H2  (BB*II*VV)     // 36864
#define NCAT  (3*HH)         // 2304

#define EFFECTS_ELEMS (M_H2*HH)
#define GRAPH_ELEMS   (BB*VV*VV)
#define ENC_ELEMS     (M_ENC*HH)

// -------- device scratch --------
__device__ __half g_varh[M_ENC*HH];
__device__ __half g_varl[M_ENC*HH];
__device__ __half g_Wench[HH*HH];
__device__ __half g_Wencl[HH*HH];
__device__ float  g_pre[M_ENC*HH];
__device__ __half g_ench[M_ENC*HH];
__device__ __half g_encl[M_ENC*HH];
__device__ __half g_Bcath[HH*NCAT];
__device__ __half g_Bcatl[HH*NCAT];
__device__ float  g_hijb[M_ENC*NCAT];     // [1536][2304]: hi | hj | hb
__device__ __half g_inth[M_HA*HH];
__device__ __half g_intl[M_HA*HH];
__device__ __half g_Wi1h[2*HH*HH];
__device__ __half g_Wi1l[2*HH*HH];
__device__ float  g_ha[M_HA*HH];
__device__ __half g_Wi2h[HH*HH];
__device__ __half g_h2h[M_H2*HH];

// ======================= fp16 tensor-core GEMMs (mma.sync) =======================
#define AS 72     // A smem row stride (64+8) halves
#define BS 136    // B smem row stride (128+8) halves
#define STG_B (64*BS)

#define STG_A_BIG (128*AS)
#define STG_BIG   (STG_A_BIG + STG_B)
#define HG_SMEM_BIG (2*STG_BIG*2)       // 71680 bytes

#define STG_A_SML (64*AS)
#define STG_SML   (STG_A_SML + STG_B)
#define HG_SMEM_SML (2*STG_SML*2)       // 53248 bytes

__device__ __forceinline__ void cp16(unsigned int dst, const void* src) {
    asm volatile("cp.async.cg.shared.global [%0], [%1], 16;\n" :: "r"(dst), "l"(src));
}

// ---- warp-level compute, 32x64 warp tile (used by small variant) ----
__device__ __forceinline__ void mma_chunk(
    unsigned int aBuf, unsigned int bBuf, int wm, int wn, int lane,
    float acc[2][8][4])
{
    #pragma unroll
    for (int kk = 0; kk < 64; kk += 16) {
        unsigned int afr0[4], afr1[4];
        {
            int row = wm*32 + (lane & 15);
            int col = kk + ((lane >> 4) << 3);
            unsigned int addr = aBuf + (unsigned int)(row*AS + col)*2u;
            asm volatile("ldmatrix.sync.aligned.m8n8.x4.shared.b16 {%0,%1,%2,%3}, [%4];"
                : "=r"(afr0[0]), "=r"(afr0[1]), "=r"(afr0[2]), "=r"(afr0[3]) : "r"(addr));
        }
        {
            int row = wm*32 + 16 + (lane & 15);
            int col = kk + ((lane >> 4) << 3);
            unsigned int addr = aBuf + (unsigned int)(row*AS + col)*2u;
            asm volatile("ldmatrix.sync.aligned.m8n8.x4.shared.b16 {%0,%1,%2,%3}, [%4];"
                : "=r"(afr1[0]), "=r"(afr1[1]), "=r"(afr1[2]), "=r"(afr1[3]) : "r"(addr));
        }
        unsigned int bfr[8][2];
        #pragma unroll
        for (int nt2 = 0; nt2 < 4; nt2++) {
            int r = kk + (lane & 15);
            int col = wn*64 + nt2*16 + ((lane >> 4) << 3);
            unsigned int addr = bBuf + (unsigned int)(r*BS + col)*2u;
            asm volatile("ldmatrix.sync.aligned.m8n8.x4.trans.shared.b16 {%0,%1,%2,%3}, [%4];"
                : "=r"(bfr[2*nt2][0]), "=r"(bfr[2*nt2][1]),
                  "=r"(bfr[2*nt2+1][0]), "=r"(bfr[2*nt2+1][1]) : "r"(addr));
        }
        #pragma unroll
        for (int nt = 0; nt < 8; nt++) {
            asm volatile("mma.sync.aligned.m16n8k16.row.col.f32.f16.f16.f32 "
                "{%0,%1,%2,%3},{%4,%5,%6,%7},{%8,%9},{%0,%1,%2,%3};"
                : "+f"(acc[0][nt][0]), "+f"(acc[0][nt][1]), "+f"(acc[0][nt][2]), "+f"(acc[0][nt][3])
                : "r"(afr0[0]), "r"(afr0[1]), "r"(afr0[2]), "r"(afr0[3]),
                  "r"(bfr[nt][0]), "r"(bfr[nt][1]));
            asm volatile("mma.sync.aligned.m16n8k16.row.col.f32.f16.f16.f32 "
                "{%0,%1,%2,%3},{%4,%5,%6,%7},{%8,%9},{%0,%1,%2,%3};"
                : "+f"(acc[1][nt][0]), "+f"(acc[1][nt][1]), "+f"(acc[1][nt][2]), "+f"(acc[1][nt][3])
                : "r"(afr1[0]), "r"(afr1[1]), "r"(afr1[2]), "r"(afr1[3]),
                  "r"(bfr[nt][0]), "r"(bfr[nt][1]));
        }
    }
}

__device__ __forceinline__ void epilogue(
    float* __restrict__ C, const float* __restrict__ bias,
    int N, int bx, int byBase, int wm, int wn, int lane,
    float acc[2][8][4])
{
    float* Cb = C + (size_t)byBase * N + bx * 128;
    const float* biasb = bias ? (bias + bx * 128) : nullptr;
    #pragma unroll
    for (int mt = 0; mt < 2; mt++) {
        #pragma unroll
        for (int nt = 0; nt < 8; nt++) {
            int r0 = wm*32 + mt*16 + (lane >> 2);
            int c0 = wn*64 + nt*8 + (lane & 3)*2;
            float2 v0 = make_float2(acc[mt][nt][0], acc[mt][nt][1]);
            float2 v1 = make_float2(acc[mt][nt][2], acc[mt][nt][3]);
            if (biasb) {
                float2 bv = *(const float2*)(biasb + c0);
                v0.x += bv.x; v0.y += bv.y; v1.x += bv.x; v1.y += bv.y;
            }
            *(float2*)(Cb + (size_t)r0 * N + c0) = v0;
            *(float2*)(Cb + (size_t)(r0 + 8) * N + c0) = v1;
        }
    }
}

// ---------------- big2 variant: BM=128 BN=128 BK=64, 128 threads, 4 warps (2Mx2N),
// warp tile 64x64 -> 32 MMAs per 8 LDSM per kk-step ----------------
__device__ __forceinline__ void load64_big2(unsigned int aB, unsigned int bB,
    const __half* __restrict__ Ag, const __half* __restrict__ Bg,
    int k0, int K, int N, int tid)
{
    #pragma unroll
    for (int it = 0; it < 8; it++) {              // A: 128 rows x 8 chunks = 1024
        int q = tid + it*128;
        int row = q >> 3, cc = q & 7;
        cp16(aB + (unsigned int)(row*AS + cc*8)*2u, Ag + (size_t)row * K + k0 + cc*8);
    }
    #pragma unroll
    for (int it = 0; it < 8; it++) {              // B: 64 rows x 16 chunks = 1024
        int q = tid + it*128;
        int row = q >> 4, cc = q & 15;
        cp16(bB + (unsigned int)(row*BS + cc*8)*2u, Bg + (size_t)(k0 + row) * N + cc*8);
    }
}

__global__ __launch_bounds__(128, 2) void hgemm_big2(
    const __half* __restrict__ A0, const __half* __restrict__ B0,
    const float* __restrict__ bias, float* __restrict__ C,
    int M, int N, int K)
{
    extern __shared__ __align__(16) __half sm[];
    const int bx = blockIdx.x, by = blockIdx.y;
    const int tid = threadIdx.x;
    const int lane = tid & 31, w = tid >> 5;
    const int wm = w & 1, wn = w >> 1;     // 2M x 2N warps, warp tile 64x64

    const unsigned int sbase = (unsigned int)__cvta_generic_to_shared(sm);
    const unsigned int aS[2] = {sbase,                           sbase + (unsigned)STG_BIG*2u};
    const unsigned int bS[2] = {sbase + (unsigned)STG_A_BIG*2u,  sbase + (unsigned)(STG_BIG + STG_A_BIG)*2u};

    const int total = K >> 6;
    const __half* Ag = A0 + (size_t)by*128*K;
    const __half* Bg = B0 + bx*128;

    float acc[4][8][4];
    #pragma unroll
    for (int mt = 0; mt < 4; mt++)
        #pragma unroll
        for (int nt = 0; nt < 8; nt++)
            #pragma unroll
            for (int q = 0; q < 4; q++) acc[mt][nt][q] = 0.f;

    load64_big2(aS[0], bS[0], Ag, Bg, 0, K, N, tid);
    asm volatile("cp.async.commit_group;\n" ::);

    for (int c = 0; c < total; c++) {
        const int buf = c & 1;
        if (c + 1 < total) {
            load64_big2(aS[buf^1], bS[buf^1], Ag, Bg, (c+1)*64, K, N, tid);
            asm volatile("cp.async.commit_group;\n" ::);
            asm volatile("cp.async.wait_group 1;\n" ::);
        } else {
            asm volatile("cp.async.wait_group 0;\n" ::);
        }
        __syncthreads();

        #pragma unroll
        for (int kk = 0; kk < 64; kk += 16) {
            unsigned int afr[4][4];
            #pragma unroll
            for (int mt = 0; mt < 4; mt++) {
                int row = wm*64 + mt*16 + (lane & 15);
                int col = kk + ((lane >> 4) << 3);
                unsigned int addr = aS[buf] + (unsigned int)(row*AS + col)*2u;
                asm volatile("ldmatrix.sync.aligned.m8n8.x4.shared.b16 {%0,%1,%2,%3}, [%4];"
                    : "=r"(afr[mt][0]), "=r"(afr[mt][1]), "=r"(afr[mt][2]), "=r"(afr[mt][3]) : "r"(addr));
            }
            unsigned int bfr[8][2];
            #pragma unroll
            for (int nt2 = 0; nt2 < 4; nt2++) {
                int r = kk + (lane & 15);
                int col = wn*64 + nt2*16 + ((lane >> 4) << 3);
                unsigned int addr = bS[buf] + (unsigned int)(r*BS + col)*2u;
                asm volatile("ldmatrix.sync.aligned.m8n8.x4.trans.shared.b16 {%0,%1,%2,%3}, [%4];"
                    : "=r"(bfr[2*nt2][0]), "=r"(bfr[2*nt2][1]),
                      "=r"(bfr[2*nt2+1][0]), "=r"(bfr[2*nt2+1][1]) : "r"(addr));
            }
            #pragma unroll
            for (int mt = 0; mt < 4; mt++)
                #pragma unroll
                for (int nt = 0; nt < 8; nt++)
                    asm volatile("mma.sync.aligned.m16n8k16.row.col.f32.f16.f16.f32 "
                        "{%0,%1,%2,%3},{%4,%5,%6,%7},{%8,%9},{%0,%1,%2,%3};"
                        : "+f"(acc[mt][nt][0]), "+f"(acc[mt][nt][1]), "+f"(acc[mt][nt][2]), "+f"(acc[mt][nt][3])
                        : "r"(afr[mt][0]), "r"(afr[mt][1]), "r"(afr[mt][2]), "r"(afr[mt][3]),
                          "r"(bfr[nt][0]), "r"(bfr[nt][1]));
        }
        __syncthreads();
    }

    // epilogue: 64x64 warp tile
    float* Cb = C + (size_t)(by * 128) * N + bx * 128;
    const float* biasb = bias ? (bias + bx * 128) : nullptr;
    #pragma unroll
    for (int mt = 0; mt < 4; mt++) {
        #pragma unroll
        for (int nt = 0; nt < 8; nt++) {
            int r0 = wm*64 + mt*16 + (lane >> 2);
            int c0 = wn*64 + nt*8 + (lane & 3)*2;
            float2 v0 = make_float2(acc[mt][nt][0], acc[mt][nt][1]);
            float2 v1 = make_float2(acc[mt][nt][2], acc[mt][nt][3]);
            if (biasb) {
                float2 bv = *(const float2*)(biasb + c0);
                v0.x += bv.x; v0.y += bv.y; v1.x += bv.x; v1.y += bv.y;
            }
            *(float2*)(Cb + (size_t)r0 * N + c0) = v0;
            *(float2*)(Cb + (size_t)(r0 + 8) * N + c0) = v1;
        }
    }
}

// ---------------- small variant core (BM=64, 128 threads, 2-stage) ----------------
__device__ __forceinline__ void load64_sml(unsigned int aB, unsigned int bB,
    const __half* __restrict__ Ag, const __half* __restrict__ Bg,
    int k0, int K, int N, int tid)
{
    #pragma unroll
    for (int it = 0; it < 4; it++) {
        int q = tid + it*128;
        int row = q >> 3, cc = q & 7;
        cp16(aB + (unsigned int)(row*AS + cc*8)*2u, Ag + (size_t)row * K + k0 + cc*8);
    }
    #pragma unroll
    for (int it = 0; it < 8; it++) {
        int q = tid + it*128;
        int row = q >> 4, cc = q & 15;
        cp16(bB + (unsigned int)(row*BS + cc*8)*2u, Bg + (size_t)(k0 + row) * N + cc*8);
    }
}

__device__ __forceinline__ void sml_body(
    const __half* A0, const __half* A1, const __half* B0, const __half* B1,
    int npairs, const float* bias, float* C, int N, int K, int by, int bx)
{
    extern __shared__ __align__(16) __half sm[];
    const int tid = threadIdx.x;
    const int lane = tid & 31, w = tid >> 5;
    const int wm = w & 1, wn = w >> 1;

    const unsigned int sbase = (unsigned int)__cvta_generic_to_shared(sm);
    const unsigned int aS[2] = {sbase,                           sbase + (unsigned)STG_SML*2u};
    const unsigned int bS[2] = {sbase + (unsigned)STG_A_SML*2u,  sbase + (unsigned)(STG_SML + STG_A_SML)*2u};

    const __half* Ap[3] = {A0, A1, A0};
    const __half* Bp[3] = {B0, B0, B1};
    const int kch = K >> 6;
    const int total = npairs * kch;

    float acc[2][8][4];
    #pragma unroll
    for (int mt = 0; mt < 2; mt++)
        #pragma unroll
        for (int nt = 0; nt < 8; nt++)
            #pragma unroll
            for (int q = 0; q < 4; q++) acc[mt][nt][q] = 0.f;

    load64_sml(aS[0], bS[0], Ap[0] + (size_t)by*64*K, Bp[0] + bx*128, 0, K, N, tid);
    asm volatile("cp.async.commit_group;\n" ::);

    for (int c = 0; c < total; c++) {
        const int buf = c & 1;
        if (c + 1 < total) {
            const int cc = c + 1;
            const int p = cc / kch, kc = cc % kch;
            load64_sml(aS[buf^1], bS[buf^1], Ap[p] + (size_t)by*64*K, Bp[p] + bx*128, kc*64, K, N, tid);
            asm volatile("cp.async.commit_group;\n" ::);
            asm volatile("cp.async.wait_group 1;\n" ::);
        } else {
            asm volatile("cp.async.wait_group 0;\n" ::);
        }
        __syncthreads();
        mma_chunk(aS[buf], bS[buf], wm, wn, lane, acc);
        __syncthreads();
    }

    epilogue(C, bias, N, bx, by*64, wm, wn, lane, acc);
}

__global__ __launch_bounds__(128, 4) void hgemm_sml(
    const __half* __restrict__ A0, const __half* __restrict__ A1,
    const __half* __restrict__ B0, const __half* __restrict__ B1,
    int npairs, const float* __restrict__ bias, float* __restrict__ C,
    int M, int N, int K)
{
    sml_body(A0, A1, B0, B1, npairs, bias, C, N, K, blockIdx.y, blockIdx.x);
}

__global__ __launch_bounds__(128, 4) void hgemm_sml_b2(
    const __half* __restrict__ A0a, const __half* __restrict__ A1a,
    const __half* __restrict__ B0a, const __half* __restrict__ B1a,
    const float* __restrict__ biasa, float* __restrict__ Ca, int tilesA,
    const __half* __restrict__ A0b, const __half* __restrict__ A1b,
    const __half* __restrict__ B0b, const __half* __restrict__ B1b,
    const float* __restrict__ biasb, float* __restrict__ Cb,
    int N, int K)
{
    const int nbx = N / 128;
    const int tile = blockIdx.x / nbx;
    const int bx   = blockIdx.x % nbx;
    if (tile < tilesA) {
        sml_body(A0a, A1a, B0a, B1a, 3, biasa, Ca, N, K, tile, bx);
    } else {
        sml_body(A0b, A1b, B0b, B1b, 3, biasb, Cb, N, K, tile - tilesA, bx);
    }
}

// ================= merged prep (all converts in ONE launch) =================
#define NW (HH*HH)
#define N_VAR (M_ENC*HH)
#define N_INT (M_HA*HH)
#define PREP_TOTAL (N_VAR + N_INT + 4*NW + HH*NCAT)

__global__ void prep_all(
    const float* __restrict__ variables, const float* __restrict__ interventions,
    const float* __restrict__ W_enc, const float* __restrict__ Wi1,
    const float* __restrict__ Wi2,   const float* __restrict__ Wg1,
    __half* __restrict__ varh, __half* __restrict__ varl,
    __half* __restrict__ inth, __half* __restrict__ intl,
    __half* __restrict__ Wench, __half* __restrict__ Wencl,
    __half* __restrict__ Wi1h,  __half* __restrict__ Wi1l,
    __half* __restrict__ Wi2h,
    __half* __restrict__ Bcath, __half* __restrict__ Bcatl)
{
    int i = blockIdx.x * 256 + threadIdx.x;
    if (i < N_VAR) {
        float v = variables[i];
        __half h = __float2half_rn(v);
        varh[i] = h; varl[i] = __float2half_rn(v - __half2float(h));
        return;
    }
    i -= N_VAR;
    if (i < N_INT) {
        float v = interventions[i];
        __half h = __float2half_rn(v);
        inth[i] = h; intl[i] = __float2half_rn(v - __half2float(h));
        return;
    }
    i -= N_INT;
    if (i < NW) {
        float v = W_enc[i];
        __half h = __float2half_rn(v);
        Wench[i] = h; Wencl[i] = __float2half_rn(v - __half2float(h));
        return;
    }
    i -= NW;
    if (i < 2*NW) {
        float v = Wi1[i];
        __half h = __float2half_rn(v);
        Wi1h[i] = h; Wi1l[i] = __float2half_rn(v - __half2float(h));
        return;
    }
    i -= 2*NW;
    if (i < NW) {
        Wi2h[i] = __float2half_rn(Wi2[i]);
        return;
    }
    i -= NW;
    if (i < HH * NCAT) {
        int r = i / NCAT, c = i % NCAT;
        float v;
        if (c < HH)            v = Wg1[(size_t)r * HH + c];
        else if (c < 2 * HH)   v = Wg1[(size_t)(HH + r) * HH + (c - HH)];
        else                   v = Wi1[(size_t)(HH + r) * HH + (c - 2 * HH)];
        __half h = __float2half_rn(v);
        Bcath[i] = h; Bcatl[i] = __float2half_rn(v - __half2float(h));
    }
}

// ================= reductions =================
__device__ __forceinline__ float blockSum256(float v) {
    #pragma unroll
    for (int o = 16; o > 0; o >>= 1) v += __shfl_down_sync(0xffffffffu, v, o);
    __shared__ float sh[9];
    int lane = threadIdx.x & 31, w = threadIdx.x >> 5;
    __syncthreads();
    if (lane == 0) sh[w] = v;
    __syncthreads();
    if (threadIdx.x == 0) {
        float t = 0.f;
        #pragma unroll
        for (int k = 0; k < 8; k++) t += sh[k];
        sh[8] = t;
    }
    __syncthreads();
    return sh[8];
}

__device__ __forceinline__ float2 blockSum2(float a, float b) {
    #pragma unroll
    for (int o = 16; o > 0; o >>= 1) {
        a += __shfl_down_sync(0xffffffffu, a, o);
        b += __shfl_down_sync(0xffffffffu, b, o);
    }
    __shared__ float2 sh2[9];
    int lane = threadIdx.x & 31, w = threadIdx.x >> 5;
    __syncthreads();
    if (lane == 0) sh2[w] = make_float2(a, b);
    __syncthreads();
    if (threadIdx.x == 0) {
        float ta = 0.f, tb = 0.f;
        #pragma unroll
        for (int k = 0; k < 8; k++) { ta += sh2[k].x; tb += sh2[k].y; }
        sh2[8] = make_float2(ta, tb);
    }
    __syncthreads();
    return sh2[8];
}

__global__ __launch_bounds__(256) void ln_relu_kernel(
    const float* __restrict__ X, const float* __restrict__ gamma,
    const float* __restrict__ beta, float* __restrict__ Y,
    __half* __restrict__ Yh, __half* __restrict__ Yl)
{
    const int row = blockIdx.x;
    const float* x = X + (size_t)row * HH;
    const int t = threadIdx.x;
    float x0 = x[t], x1 = x[t + 256], x2 = x[t + 512];
    float2 sq = blockSum2(x0 + x1 + x2, x0*x0 + x1*x1 + x2*x2);
    float mu = sq.x * (1.f / HH);
    float var = sq.y * (1.f / HH) - mu * mu;
    float inv = rsqrtf(var + 1e-5f);
    float y0 = fmaxf((x0 - mu) * inv * gamma[t]       + beta[t],       0.f);
    float y1 = fmaxf((x1 - mu) * inv * gamma[t + 256] + beta[t + 256], 0.f);
    float y2 = fmaxf((x2 - mu) * inv * gamma[t + 512] + beta[t + 512], 0.f);
    size_t o = (size_t)row * HH;
    Y[o + t] = y0; Y[o + t + 256] = y1; Y[o + t + 512] = y2;
    __half h0 = __float2half_rn(y0), h1 = __float2half_rn(y1), h2v = __float2half_rn(y2);
    Yh[o + t] = h0; Yh[o + t + 256] = h1; Yh[o + t + 512] = h2v;
    Yl[o + t]       = __float2half_rn(y0 - __half2float(h0));
    Yl[o + t + 256] = __float2half_rn(y1 - __half2float(h1));
    Yl[o + t + 512] = __float2half_rn(y2 - __half2float(h2v));
}

#define JCH 12   // j-chunk size (48/4)

// merged graph + h2: grid (VV, BB, 8); z<4 -> graph jc=z; z>=4 -> h2 jc=z-4 (x<II only)
__global__ __launch_bounds__(256) void pairwise_kernel(
    const float* __restrict__ hijb, const float* __restrict__ ha,
    const float* __restrict__ bg1, const float* __restrict__ g_g,
    const float* __restrict__ b_g, const float* __restrict__ Wg2,
    const float* __restrict__ bg2,
    const float* __restrict__ bi1, const float* __restrict__ g_i,
    const float* __restrict__ b_i,
    float* __restrict__ graph, __half* __restrict__ h2out)
{
    const int b = blockIdx.y;
    const int t = threadIdx.x;
    const int z = blockIdx.z;

    if (z < 4) {
        const int i = blockIdx.x, jc = z;
        const float* xi = hijb + (size_t)(b * VV + i) * NCAT;
        const float a0 = xi[t]       + bg1[t];
        const float a1 = xi[t + 256] + bg1[t + 256];
        const float a2 = xi[t + 512] + bg1[t + 512];
        const float gg0 = g_g[t], gg1 = g_g[t+256], gg2 = g_g[t+512];
        const float bb0 = b_g[t],  bb1 = b_g[t+256],  bb2 = b_g[t+512];
        const float w0 = Wg2[t], w1 = Wg2[t+256], w9 = Wg2[t+512];
        const float b20 = bg2[0];
        float* orow = graph + (size_t)(b * VV + i) * VV;

        for (int j = jc*JCH; j < jc*JCH + JCH; j++) {
            const float* xj = hijb + (size_t)(b * VV + j) * NCAT + HH;
            float x0 = a0 + xj[t];
            float x1 = a1 + xj[t + 256];
            float x2 = a2 + xj[t + 512];
            float2 sq = blockSum2(x0 + x1 + x2, x0*x0 + x1*x1 + x2*x2);
            float mu = sq.x * (1.f / HH);
            float var = sq.y * (1.f / HH) - mu * mu;
            float inv = rsqrtf(var + 1e-5f);
            float y0 = fmaxf((x0 - mu) * inv * gg0 + bb0, 0.f);
            float y1 = fmaxf((x1 - mu) * inv * gg1 + bb1, 0.f);
            float y2 = fmaxf((x2 - mu) * inv * gg2 + bb2, 0.f);
            float d = blockSum256(y0 * w0 + y1 * w1 + y2 * w9);
            if (t == 0)
                orow[j] = (i == j) ? 0.f : 1.f / (1.f + expf(-(d + b20)));
        }
    } else {
        const int i = blockIdx.x;
        if (i >= II) return;
        const int jc = z - 4;
        const float* xa = ha + (size_t)(b * II + i) * HH;
        const float a0 = xa[t]       + bi1[t];
        const float a1 = xa[t + 256] + bi1[t + 256];
        const float a2 = xa[t + 512] + bi1[t + 512];
        const float gg0 = g_i[t], gg1 = g_i[t+256], gg2 = g_i[t+512];
        const float bb0 = b_i[t],  bb1 = b_i[t+256],  bb2 = b_i[t+512];
        __half* yb = h2out + (size_t)(b * II + i) * VV * HH;

        for (int j = jc*JCH; j < jc*JCH + JCH; j++) {
            const float* xb = hijb + (size_t)(b * VV + j) * NCAT + 2 * HH;
            float x0 = a0 + xb[t];
            float x1 = a1 + xb[t + 256];
            float x2 = a2 + xb[t + 512];
            float2 sq = blockSum2(x0 + x1 + x2, x0*x0 + x1*x1 + x2*x2);
            float mu = sq.x * (1.f / HH);
            float var = sq.y * (1.f / HH) - mu * mu;
            float inv = rsqrtf(var + 1e-5f);
            __half* y = yb + (size_t)j * HH;
            y[t]       = __float2half_rn(fmaxf((x0 - mu) * inv * gg0 + bb0, 0.f));
            y[t + 256] = __float2half_rn(fmaxf((x1 - mu) * inv * gg1 + bb1, 0.f));
            y[t + 512] = __float2half_rn(fmaxf((x2 - mu) * inv * gg2 + bb2, 0.f));
        }
    }
}

extern "C" void kernel_launch(void* const* d_in, const int* in_sizes, int n_in,
                              void* d_out, int out_size) {
    const float* variables     = (const float*)d_in[0];
    const float* interventions = (const float*)d_in[1];
    const float* W_enc  = (const float*)d_in[2];
    const float* b_enc  = (const float*)d_in[3];
    const float* g_enc  = (const float*)d_in[4];
    const float* be_enc = (const float*)d_in[5];
    const float* Wg1    = (const float*)d_in[6];
    const float* bg1    = (const float*)d_in[7];
    const float* g_g    = (const float*)d_in[8];
    const float* b_g    = (const float*)d_in[9];
    const float* Wg2    = (const float*)d_in[10];
    const float* bg2    = (const float*)d_in[11];
    const float* Wi1    = (const float*)d_in[12];
    const float* bi1    = (const float*)d_in[13];
    const float* g_i    = (const float*)d_in[14];
    const float* b_i    = (const float*)d_in[15];
    const float* Wi2    = (const float*)d_in[16];
    const float* bi2    = (const float*)d_in[17];

    float* effects = (float*)d_out;
    float* graph   = effects + EFFECTS_ELEMS;
    float* enc     = graph + GRAPH_ELEMS;

    __half *p_varh, *p_varl, *p_Wench, *p_Wencl, *p_ench, *p_encl;
    __half *p_Bcath, *p_Bcatl, *p_inth, *p_intl, *p_Wi1h, *p_Wi1l, *p_Wi2h, *p_h2h;
    float *p_pre, *p_hijb, *p_ha;
    cudaGetSymbolAddress((void**)&p_varh,  g_varh);
    cudaGetSymbolAddress((void**)&p_varl,  g_varl);
    cudaGetSymbolAddress((void**)&p_Wench, g_Wench);
    cudaGetSymbolAddress((void**)&p_Wencl, g_Wencl);
    cudaGetSymbolAddress((void**)&p_pre,   g_pre);
    cudaGetSymbolAddress((void**)&p_ench,  g_ench);
    cudaGetSymbolAddress((void**)&p_encl,  g_encl);
    cudaGetSymbolAddress((void**)&p_Bcath, g_Bcath);
    cudaGetSymbolAddress((void**)&p_Bcatl, g_Bcatl);
    cudaGetSymbolAddress((void**)&p_hijb,  g_hijb);
    cudaGetSymbolAddress((void**)&p_inth,  g_inth);
    cudaGetSymbolAddress((void**)&p_intl,  g_intl);
    cudaGetSymbolAddress((void**)&p_Wi1h,  g_Wi1h);
    cudaGetSymbolAddress((void**)&p_Wi1l,  g_Wi1l);
    cudaGetSymbolAddress((void**)&p_ha,    g_ha);
    cudaGetSymbolAddress((void**)&p_Wi2h,  g_Wi2h);
    cudaGetSymbolAddress((void**)&p_h2h,   g_h2h);

    cudaFuncSetAttribute(hgemm_big2,    cudaFuncAttributeMaxDynamicSharedMemorySize, HG_SMEM_BIG);
    cudaFuncSetAttribute(hgemm_sml,     cudaFuncAttributeMaxDynamicSharedMemorySize, HG_SMEM_SML);
    cudaFuncSetAttribute(hgemm_sml_b2,  cudaFuncAttributeMaxDynamicSharedMemorySize, HG_SMEM_SML);

    dim3 blk(256);
    dim3 blk128(128);

    // 1) all converts in one launch
    prep_all<<<(PREP_TOTAL + 255)/256, blk>>>(
        variables, interventions, W_enc, Wi1, Wi2, Wg1,
        p_varh, p_varl, p_inth, p_intl,
        p_Wench, p_Wencl, p_Wi1h, p_Wi1l, p_Wi2h, p_Bcath, p_Bcatl);

    // 2) pre + ha batched in one launch (216 CTAs)
    hgemm_sml_b2<<<dim3((M_ENC/64 + M_HA/64) * (HH/128)), blk128, HG_SMEM_SML>>>(
        p_varh, p_varl, p_Wench, p_Wencl, b_enc, p_pre, M_ENC/64,
        p_inth, p_intl, p_Wi1h, p_Wi1l, nullptr, p_ha,
        HH, HH);

    // 3) enc = relu(LN(pre))
    ln_relu_kernel<<<M_ENC, blk>>>(p_pre, g_enc, be_enc, enc, p_ench, p_encl);

    // 4) hijb = enc @ [Wg1a|Wg1b|Wi1b]  (3 fused pairs, 432 CTAs)
    hgemm_sml<<<dim3(NCAT/128, M_ENC/64), blk128, HG_SMEM_SML>>>(
        p_ench, p_encl, p_Bcath, p_Bcatl, 3, nullptr, p_hijb, M_ENC, NCAT, HH);

    // 5) graph + h2 merged
    pairwise_kernel<<<dim3(VV, BB, 8), blk>>>(
        p_hijb, p_ha, bg1, g_g, b_g, Wg2, bg2, bi1, g_i, b_i, graph, p_h2h);

    // 6) effects = h2 @ Wi2 + bi2 (big2: 64x64 warp tiles, 1728 CTAs)
    hgemm_big2<<<dim3(HH/128, M_H2/128), blk128, HG_SMEM_BIG>>>(
        p_h2h, p_Wi2h, bi2, effects, M_H2, HH, HH);
}

// round 12
// speedup vs baseline: 1.2083x; 1.2083x over previous
#include <cuda_runtime.h>
#include <cuda_fp16.h>
#include <cstdint>
#include <math.h>

// Problem dims
#define BB 32
#define VV 48
#define II 24
#define HH 768

#define M_ENC (BB*VV)        // 1536
#define M_HA  (BB*II)        // 768
#define M_H2  (BB*II*VV)     // 36864
#define NCAT  (3*HH)         // 2304

#define EFFECTS_ELEMS (M_H2*HH)
#define GRAPH_ELEMS   (BB*VV*VV)
#define ENC_ELEMS     (M_ENC*HH)

// -------- device scratch --------
__device__ __half g_varh[M_ENC*HH];
__device__ __half g_Wench[HH*HH];
__device__ float  g_pre[M_ENC*HH];
__device__ __half g_ench[M_ENC*HH];
__device__ __half g_Bcath[HH*NCAT];
__device__ float  g_hijb[M_ENC*NCAT];     // [1536][2304]: hi | hj | hb
__device__ __half g_inth[M_HA*HH];
__device__ __half g_Wi1h[HH*HH];          // Wi1[:H] only
__device__ float  g_ha[M_HA*HH];
__device__ __half g_Wi2h[HH*HH];
__device__ __half g_h2h[M_H2*HH];

// ======================= fp16 tensor-core GEMMs (mma.sync) =======================
// Warp microtile 32x64, mma.m16n8k16, B frags via ldmatrix.x4.trans. Single pass.
// Big variant:   BM=128 BN=128 BK=64, 256 thr, 2-stage, 71.7KB smem (2 CTA/SM)
// Small variant: BM=64  BN=128 BK=64, 128 thr, 2-stage, 53.2KB smem

#define AS 72     // A smem row stride (64+8) halves
#define BS 136    // B smem row stride (128+8) halves
#define STG_B (64*BS)

#define STG_A_BIG (128*AS)
#define STG_BIG   (STG_A_BIG + STG_B)
#define HG_SMEM_BIG (2*STG_BIG*2)       // 71680 bytes

#define STG_A_SML (64*AS)
#define STG_SML   (STG_A_SML + STG_B)
#define HG_SMEM_SML (2*STG_SML*2)       // 53248 bytes

__device__ __forceinline__ void cp16(unsigned int dst, const void* src) {
    asm volatile("cp.async.cg.shared.global [%0], [%1], 16;\n" :: "r"(dst), "l"(src));
}

// ---- warp-level compute for one 64-k chunk (32x64 warp tile) ----
__device__ __forceinline__ void mma_chunk(
    unsigned int aBuf, unsigned int bBuf, int wm, int wn, int lane,
    float acc[2][8][4])
{
    #pragma unroll
    for (int kk = 0; kk < 64; kk += 16) {
        unsigned int afr0[4], afr1[4];
        {
            int row = wm*32 + (lane & 15);
            int col = kk + ((lane >> 4) << 3);
            unsigned int addr = aBuf + (unsigned int)(row*AS + col)*2u;
            asm volatile("ldmatrix.sync.aligned.m8n8.x4.shared.b16 {%0,%1,%2,%3}, [%4];"
                : "=r"(afr0[0]), "=r"(afr0[1]), "=r"(afr0[2]), "=r"(afr0[3]) : "r"(addr));
        }
        {
            int row = wm*32 + 16 + (lane & 15);
            int col = kk + ((lane >> 4) << 3);
            unsigned int addr = aBuf + (unsigned int)(row*AS + col)*2u;
            asm volatile("ldmatrix.sync.aligned.m8n8.x4.shared.b16 {%0,%1,%2,%3}, [%4];"
                : "=r"(afr1[0]), "=r"(afr1[1]), "=r"(afr1[2]), "=r"(afr1[3]) : "r"(addr));
        }
        unsigned int bfr[8][2];
        #pragma unroll
        for (int nt2 = 0; nt2 < 4; nt2++) {
            int r = kk + (lane & 15);
            int col = wn*64 + nt2*16 + ((lane >> 4) << 3);
            unsigned int addr = bBuf + (unsigned int)(r*BS + col)*2u;
            asm volatile("ldmatrix.sync.aligned.m8n8.x4.trans.shared.b16 {%0,%1,%2,%3}, [%4];"
                : "=r"(bfr[2*nt2][0]), "=r"(bfr[2*nt2][1]),
                  "=r"(bfr[2*nt2+1][0]), "=r"(bfr[2*nt2+1][1]) : "r"(addr));
        }
        #pragma unroll
        for (int nt = 0; nt < 8; nt++) {
            asm volatile("mma.sync.aligned.m16n8k16.row.col.f32.f16.f16.f32 "
                "{%0,%1,%2,%3},{%4,%5,%6,%7},{%8,%9},{%0,%1,%2,%3};"
                : "+f"(acc[0][nt][0]), "+f"(acc[0][nt][1]), "+f"(acc[0][nt][2]), "+f"(acc[0][nt][3])
                : "r"(afr0[0]), "r"(afr0[1]), "r"(afr0[2]), "r"(afr0[3]),
                  "r"(bfr[nt][0]), "r"(bfr[nt][1]));
            asm volatile("mma.sync.aligned.m16n8k16.row.col.f32.f16.f16.f32 "
                "{%0,%1,%2,%3},{%4,%5,%6,%7},{%8,%9},{%0,%1,%2,%3};"
                : "+f"(acc[1][nt][0]), "+f"(acc[1][nt][1]), "+f"(acc[1][nt][2]), "+f"(acc[1][nt][3])
                : "r"(afr1[0]), "r"(afr1[1]), "r"(afr1[2]), "r"(afr1[3]),
                  "r"(bfr[nt][0]), "r"(bfr[nt][1]));
        }
    }
}

__device__ __forceinline__ void epilogue(
    float* __restrict__ C, const float* __restrict__ bias,
    int N, int bx, int byBase, int wm, int wn, int lane,
    float acc[2][8][4])
{
    float* Cb = C + (size_t)byBase * N + bx * 128;
    const float* biasb = bias ? (bias + bx * 128) : nullptr;
    #pragma unroll
    for (int mt = 0; mt < 2; mt++) {
        #pragma unroll
        for (int nt = 0; nt < 8; nt++) {
            int r0 = wm*32 + mt*16 + (lane >> 2);
            int c0 = wn*64 + nt*8 + (lane & 3)*2;
            float2 v0 = make_float2(acc[mt][nt][0], acc[mt][nt][1]);
            float2 v1 = make_float2(acc[mt][nt][2], acc[mt][nt][3]);
            if (biasb) {
                float2 bv = *(const float2*)(biasb + c0);
                v0.x += bv.x; v0.y += bv.y; v1.x += bv.x; v1.y += bv.y;
            }
            *(float2*)(Cb + (size_t)r0 * N + c0) = v0;
            *(float2*)(Cb + (size_t)(r0 + 8) * N + c0) = v1;
        }
    }
}

// ---------------- big variant: BM=128, 256 threads, 2-stage (round-10 proven) ----------------
__device__ __forceinline__ void load64_big(unsigned int aB, unsigned int bB,
    const __half* __restrict__ Ag, const __half* __restrict__ Bg,
    int k0, int K, int N, int tid)
{
    #pragma unroll
    for (int it = 0; it < 4; it++) {
        int q = tid + it*256;
        int row = q >> 3, cc = q & 7;
        cp16(aB + (unsigned int)(row*AS + cc*8)*2u, Ag + (size_t)row * K + k0 + cc*8);
    }
    #pragma unroll
    for (int it = 0; it < 4; it++) {
        int q = tid + it*256;
        int row = q >> 4, cc = q & 15;
        cp16(bB + (unsigned int)(row*BS + cc*8)*2u, Bg + (size_t)(k0 + row) * N + cc*8);
    }
}

__global__ __launch_bounds__(256) void hgemm_big(
    const __half* __restrict__ A0, const __half* __restrict__ B0,
    const float* __restrict__ bias, float* __restrict__ C,
    int M, int N, int K)
{
    extern __shared__ __align__(16) __half sm[];
    const int bx = blockIdx.x, by = blockIdx.y;
    const int tid = threadIdx.x;
    const int lane = tid & 31, w = tid >> 5;
    const int wm = w & 3, wn = w >> 2;

    const unsigned int sbase = (unsigned int)__cvta_generic_to_shared(sm);
    const unsigned int aS[2] = {sbase,                           sbase + (unsigned)STG_BIG*2u};
    const unsigned int bS[2] = {sbase + (unsigned)STG_A_BIG*2u,  sbase + (unsigned)(STG_BIG + STG_A_BIG)*2u};

    const int total = K >> 6;
    const __half* Ag = A0 + (size_t)by*128*K;
    const __half* Bg = B0 + bx*128;

    float acc[2][8][4];
    #pragma unroll
    for (int mt = 0; mt < 2; mt++)
        #pragma unroll
        for (int nt = 0; nt < 8; nt++)
            #pragma unroll
            for (int q = 0; q < 4; q++) acc[mt][nt][q] = 0.f;

    load64_big(aS[0], bS[0], Ag, Bg, 0, K, N, tid);
    asm volatile("cp.async.commit_group;\n" ::);

    for (int c = 0; c < total; c++) {
        const int buf = c & 1;
        if (c + 1 < total) {
            load64_big(aS[buf^1], bS[buf^1], Ag, Bg, (c+1)*64, K, N, tid);
            asm volatile("cp.async.commit_group;\n" ::);
            asm volatile("cp.async.wait_group 1;\n" ::);
        } else {
            asm volatile("cp.async.wait_group 0;\n" ::);
        }
        __syncthreads();
        mma_chunk(aS[buf], bS[buf], wm, wn, lane, acc);
        __syncthreads();
    }

    epilogue(C, bias, N, bx, by*128, wm, wn, lane, acc);
}

// ---------------- small variant core (BM=64, 128 threads, 2-stage, single pass) ----------------
__device__ __forceinline__ void load64_sml(unsigned int aB, unsigned int bB,
    const __half* __restrict__ Ag, const __half* __restrict__ Bg,
    int k0, int K, int N, int tid)
{
    #pragma unroll
    for (int it = 0; it < 4; it++) {
        int q = tid + it*128;
        int row = q >> 3, cc = q & 7;
        cp16(aB + (unsigned int)(row*AS + cc*8)*2u, Ag + (size_t)row * K + k0 + cc*8);
    }
    #pragma unroll
    for (int it = 0; it < 8; it++) {
        int q = tid + it*128;
        int row = q >> 4, cc = q & 15;
        cp16(bB + (unsigned int)(row*BS + cc*8)*2u, Bg + (size_t)(k0 + row) * N + cc*8);
    }
}

__device__ __forceinline__ void sml_body(
    const __half* A0, const __half* B0,
    const float* bias, float* C, int N, int K, int by, int bx)
{
    extern __shared__ __align__(16) __half sm[];
    const int tid = threadIdx.x;
    const int lane = tid & 31, w = tid >> 5;
    const int wm = w & 1, wn = w >> 1;

    const unsigned int sbase = (unsigned int)__cvta_generic_to_shared(sm);
    const unsigned int aS[2] = {sbase,                           sbase + (unsigned)STG_SML*2u};
    const unsigned int bS[2] = {sbase + (unsigned)STG_A_SML*2u,  sbase + (unsigned)(STG_SML + STG_A_SML)*2u};

    const int total = K >> 6;
    const __half* Ag = A0 + (size_t)by*64*K;
    const __half* Bg = B0 + bx*128;

    float acc[2][8][4];
    #pragma unroll
    for (int mt = 0; mt < 2; mt++)
        #pragma unroll
        for (int nt = 0; nt < 8; nt++)
            #pragma unroll
            for (int q = 0; q < 4; q++) acc[mt][nt][q] = 0.f;

    load64_sml(aS[0], bS[0], Ag, Bg, 0, K, N, tid);
    asm volatile("cp.async.commit_group;\n" ::);

    for (int c = 0; c < total; c++) {
        const int buf = c & 1;
        if (c + 1 < total) {
            load64_sml(aS[buf^1], bS[buf^1], Ag, Bg, (c+1)*64, K, N, tid);
            asm volatile("cp.async.commit_group;\n" ::);
            asm volatile("cp.async.wait_group 1;\n" ::);
        } else {
            asm volatile("cp.async.wait_group 0;\n" ::);
        }
        __syncthreads();
        mma_chunk(aS[buf], bS[buf], wm, wn, lane, acc);
        __syncthreads();
    }

    epilogue(C, bias, N, bx, by*64, wm, wn, lane, acc);
}

__global__ __launch_bounds__(128, 4) void hgemm_sml(
    const __half* __restrict__ A0, const __half* __restrict__ B0,
    const float* __restrict__ bias, float* __restrict__ C,
    int M, int N, int K)
{
    sml_body(A0, B0, bias, C, N, K, blockIdx.y, blockIdx.x);
}

// batched 2-problem small GEMM (pre + ha in one launch; both N=768,K=768)
__global__ __launch_bounds__(128, 4) void hgemm_sml_b2(
    const __half* __restrict__ A0a, const __half* __restrict__ B0a,
    const float* __restrict__ biasa, float* __restrict__ Ca, int tilesA,
    const __half* __restrict__ A0b, const __half* __restrict__ B0b,
    const float* __restrict__ biasb, float* __restrict__ Cb,
    int N, int K)
{
    const int nbx = N / 128;
    const int tile = blockIdx.x / nbx;
    const int bx   = blockIdx.x % nbx;
    if (tile < tilesA) {
        sml_body(A0a, B0a, biasa, Ca, N, K, tile, bx);
    } else {
        sml_body(A0b, B0b, biasb, Cb, N, K, tile - tilesA, bx);
    }
}

// ================= merged prep (all converts in ONE launch, hi-only) =================
#define NW (HH*HH)
#define N_VAR (M_ENC*HH)
#define N_INT (M_HA*HH)
#define PREP_TOTAL (N_VAR + N_INT + 3*NW + HH*NCAT)

__global__ void prep_all(
    const float* __restrict__ variables, const float* __restrict__ interventions,
    const float* __restrict__ W_enc, const float* __restrict__ Wi1,
    const float* __restrict__ Wi2,   const float* __restrict__ Wg1,
    __half* __restrict__ varh, __half* __restrict__ inth,
    __half* __restrict__ Wench, __half* __restrict__ Wi1h,
    __half* __restrict__ Wi2h,  __half* __restrict__ Bcath)
{
    int i = blockIdx.x * 256 + threadIdx.x;
    if (i < N_VAR) { varh[i] = __float2half_rn(variables[i]); return; }
    i -= N_VAR;
    if (i < N_INT) { inth[i] = __float2half_rn(interventions[i]); return; }
    i -= N_INT;
    if (i < NW) { Wench[i] = __float2half_rn(W_enc[i]); return; }
    i -= NW;
    if (i < NW) { Wi1h[i] = __float2half_rn(Wi1[i]); return; }   // Wi1[:H] rows
    i -= NW;
    if (i < NW) { Wi2h[i] = __float2half_rn(Wi2[i]); return; }
    i -= NW;
    if (i < HH * NCAT) {
        int r = i / NCAT, c = i % NCAT;
        float v;
        if (c < HH)            v = Wg1[(size_t)r * HH + c];
        else if (c < 2 * HH)   v = Wg1[(size_t)(HH + r) * HH + (c - HH)];
        else                   v = Wi1[(size_t)(HH + r) * HH + (c - 2 * HH)];
        Bcath[i] = __float2half_rn(v);
    }
}

// ================= reductions =================
__device__ __forceinline__ float blockSum256(float v) {
    #pragma unroll
    for (int o = 16; o > 0; o >>= 1) v += __shfl_down_sync(0xffffffffu, v, o);
    __shared__ float sh[9];
    int lane = threadIdx.x & 31, w = threadIdx.x >> 5;
    __syncthreads();
    if (lane == 0) sh[w] = v;
    __syncthreads();
    if (threadIdx.x == 0) {
        float t = 0.f;
        #pragma unroll
        for (int k = 0; k < 8; k++) t += sh[k];
        sh[8] = t;
    }
    __syncthreads();
    return sh[8];
}

__device__ __forceinline__ float2 blockSum2(float a, float b) {
    #pragma unroll
    for (int o = 16; o > 0; o >>= 1) {
        a += __shfl_down_sync(0xffffffffu, a, o);
        b += __shfl_down_sync(0xffffffffu, b, o);
    }
    __shared__ float2 sh2[9];
    int lane = threadIdx.x & 31, w = threadIdx.x >> 5;
    __syncthreads();
    if (lane == 0) sh2[w] = make_float2(a, b);
    __syncthreads();
    if (threadIdx.x == 0) {
        float ta = 0.f, tb = 0.f;
        #pragma unroll
        for (int k = 0; k < 8; k++) { ta += sh2[k].x; tb += sh2[k].y; }
        sh2[8] = make_float2(ta, tb);
    }
    __syncthreads();
    return sh2[8];
}

__global__ __launch_bounds__(256) void ln_relu_kernel(
    const float* __restrict__ X, const float* __restrict__ gamma,
    const float* __restrict__ beta, float* __restrict__ Y,
    __half* __restrict__ Yh)
{
    const int row = blockIdx.x;
    const float* x = X + (size_t)row * HH;
    const int t = threadIdx.x;
    float x0 = x[t], x1 = x[t + 256], x2 = x[t + 512];
    float2 sq = blockSum2(x0 + x1 + x2, x0*x0 + x1*x1 + x2*x2);
    float mu = sq.x * (1.f / HH);
    float var = sq.y * (1.f / HH) - mu * mu;
    float inv = rsqrtf(var + 1e-5f);
    float y0 = fmaxf((x0 - mu) * inv * gamma[t]       + beta[t],       0.f);
    float y1 = fmaxf((x1 - mu) * inv * gamma[t + 256] + beta[t + 256], 0.f);
    float y2 = fmaxf((x2 - mu) * inv * gamma[t + 512] + beta[t + 512], 0.f);
    size_t o = (size_t)row * HH;
    Y[o + t] = y0; Y[o + t + 256] = y1; Y[o + t + 512] = y2;
    Yh[o + t]       = __float2half_rn(y0);
    Yh[o + t + 256] = __float2half_rn(y1);
    Yh[o + t + 512] = __float2half_rn(y2);
}

#define JCH 12   // j-chunk size (48/4)

// merged graph + h2: grid (VV, BB, 8); z<4 -> graph jc=z; z>=4 -> h2 jc=z-4 (x<II only)
__global__ __launch_bounds__(256) void pairwise_kernel(
    const float* __restrict__ hijb, const float* __restrict__ ha,
    const float* __restrict__ bg1, const float* __restrict__ g_g,
    const float* __restrict__ b_g, const float* __restrict__ Wg2,
    const float* __restrict__ bg2,
    const float* __restrict__ bi1, const float* __restrict__ g_i,
    const float* __restrict__ b_i,
    float* __restrict__ graph, __half* __restrict__ h2out)
{
    const int b = blockIdx.y;
    const int t = threadIdx.x;
    const int z = blockIdx.z;

    if (z < 4) {
        const int i = blockIdx.x, jc = z;
        const float* xi = hijb + (size_t)(b * VV + i) * NCAT;
        const float a0 = xi[t]       + bg1[t];
        const float a1 = xi[t + 256] + bg1[t + 256];
        const float a2 = xi[t + 512] + bg1[t + 512];
        const float gg0 = g_g[t], gg1 = g_g[t+256], gg2 = g_g[t+512];
        const float bb0 = b_g[t],  bb1 = b_g[t+256],  bb2 = b_g[t+512];
        const float w0 = Wg2[t], w1 = Wg2[t+256], w9 = Wg2[t+512];
        const float b20 = bg2[0];
        float* orow = graph + (size_t)(b * VV + i) * VV;

        for (int j = jc*JCH; j < jc*JCH + JCH; j++) {
            const float* xj = hijb + (size_t)(b * VV + j) * NCAT + HH;
            float x0 = a0 + xj[t];
            float x1 = a1 + xj[t + 256];
            float x2 = a2 + xj[t + 512];
            float2 sq = blockSum2(x0 + x1 + x2, x0*x0 + x1*x1 + x2*x2);
            float mu = sq.x * (1.f / HH);
            float var = sq.y * (1.f / HH) - mu * mu;
            float inv = rsqrtf(var + 1e-5f);
            float y0 = fmaxf((x0 - mu) * inv * gg0 + bb0, 0.f);
            float y1 = fmaxf((x1 - mu) * inv * gg1 + bb1, 0.f);
            float y2 = fmaxf((x2 - mu) * inv * gg2 + bb2, 0.f);
            float d = blockSum256(y0 * w0 + y1 * w1 + y2 * w9);
            if (t == 0)
                orow[j] = (i == j) ? 0.f : 1.f / (1.f + expf(-(d + b20)));
        }
    } else {
        const int i = blockIdx.x;
        if (i >= II) return;
        const int jc = z - 4;
        const float* xa = ha + (size_t)(b * II + i) * HH;
        const float a0 = xa[t]       + bi1[t];
        const float a1 = xa[t + 256] + bi1[t + 256];
        const float a2 = xa[t + 512] + bi1[t + 512];
        const float gg0 = g_i[t], gg1 = g_i[t+256], gg2 = g_i[t+512];
        const float bb0 = b_i[t],  bb1 = b_i[t+256],  bb2 = b_i[t+512];
        __half* yb = h2out + (size_t)(b * II + i) * VV * HH;

        for (int j = jc*JCH; j < jc*JCH + JCH; j++) {
            const float* xb = hijb + (size_t)(b * VV + j) * NCAT + 2 * HH;
            float x0 = a0 + xb[t];
            float x1 = a1 + xb[t + 256];
            float x2 = a2 + xb[t + 512];
            float2 sq = blockSum2(x0 + x1 + x2, x0*x0 + x1*x1 + x2*x2);
            float mu = sq.x * (1.f / HH);
            float var = sq.y * (1.f / HH) - mu * mu;
            float inv = rsqrtf(var + 1e-5f);
            __half* y = yb + (size_t)j * HH;
            y[t]       = __float2half_rn(fmaxf((x0 - mu) * inv * gg0 + bb0, 0.f));
            y[t + 256] = __float2half_rn(fmaxf((x1 - mu) * inv * gg1 + bb1, 0.f));
            y[t + 512] = __float2half_rn(fmaxf((x2 - mu) * inv * gg2 + bb2, 0.f));
        }
    }
}

extern "C" void kernel_launch(void* const* d_in, const int* in_sizes, int n_in,
                              void* d_out, int out_size) {
    const float* variables     = (const float*)d_in[0];
    const float* interventions = (const float*)d_in[1];
    const float* W_enc  = (const float*)d_in[2];
    const float* b_enc  = (const float*)d_in[3];
    const float* g_enc  = (const float*)d_in[4];
    const float* be_enc = (const float*)d_in[5];
    const float* Wg1    = (const float*)d_in[6];
    const float* bg1    = (const float*)d_in[7];
    const float* g_g    = (const float*)d_in[8];
    const float* b_g    = (const float*)d_in[9];
    const float* Wg2    = (const float*)d_in[10];
    const float* bg2    = (const float*)d_in[11];
    const float* Wi1    = (const float*)d_in[12];
    const float* bi1    = (const float*)d_in[13];
    const float* g_i    = (const float*)d_in[14];
    const float* b_i    = (const float*)d_in[15];
    const float* Wi2    = (const float*)d_in[16];
    const float* bi2    = (const float*)d_in[17];

    float* effects = (float*)d_out;
    float* graph   = effects + EFFECTS_ELEMS;
    float* enc     = graph + GRAPH_ELEMS;

    __half *p_varh, *p_Wench, *p_ench, *p_Bcath, *p_inth, *p_Wi1h, *p_Wi2h, *p_h2h;
    float *p_pre, *p_hijb, *p_ha;
    cudaGetSymbolAddress((void**)&p_varh,  g_varh);
    cudaGetSymbolAddress((void**)&p_Wench, g_Wench);
    cudaGetSymbolAddress((void**)&p_pre,   g_pre);
    cudaGetSymbolAddress((void**)&p_ench,  g_ench);
    cudaGetSymbolAddress((void**)&p_Bcath, g_Bcath);
    cudaGetSymbolAddress((void**)&p_hijb,  g_hijb);
    cudaGetSymbolAddress((void**)&p_inth,  g_inth);
    cudaGetSymbolAddress((void**)&p_Wi1h,  g_Wi1h);
    cudaGetSymbolAddress((void**)&p_ha,    g_ha);
    cudaGetSymbolAddress((void**)&p_Wi2h,  g_Wi2h);
    cudaGetSymbolAddress((void**)&p_h2h,   g_h2h);

    cudaFuncSetAttribute(hgemm_big,    cudaFuncAttributeMaxDynamicSharedMemorySize, HG_SMEM_BIG);
    cudaFuncSetAttribute(hgemm_sml,    cudaFuncAttributeMaxDynamicSharedMemorySize, HG_SMEM_SML);
    cudaFuncSetAttribute(hgemm_sml_b2, cudaFuncAttributeMaxDynamicSharedMemorySize, HG_SMEM_SML);

    dim3 blk(256);
    dim3 blk128(128);

    // 1) all converts in one launch (hi-only)
    prep_all<<<(PREP_TOTAL + 255)/256, blk>>>(
        variables, interventions, W_enc, Wi1, Wi2, Wg1,
        p_varh, p_inth, p_Wench, p_Wi1h, p_Wi2h, p_Bcath);

    // 2) pre + ha batched in one launch (216 CTAs, single pass)
    hgemm_sml_b2<<<dim3((M_ENC/64 + M_HA/64) * (HH/128)), blk128, HG_SMEM_SML>>>(
        p_varh, p_Wench, b_enc, p_pre, M_ENC/64,
        p_inth, p_Wi1h, nullptr, p_ha,
        HH, HH);

    // 3) enc = relu(LN(pre))
    ln_relu_kernel<<<M_ENC, blk>>>(p_pre, g_enc, be_enc, enc, p_ench);

    // 4) hijb = enc @ [Wg1a|Wg1b|Wi1b]  (432 CTAs, single pass)
    hgemm_sml<<<dim3(NCAT/128, M_ENC/64), blk128, HG_SMEM_SML>>>(
        p_ench, p_Bcath, nullptr, p_hijb, M_ENC, NCAT, HH);

    // 5) graph + h2 merged
    pairwise_kernel<<<dim3(VV, BB, 8), blk>>>(
        p_hijb, p_ha, bg1, g_g, b_g, Wg2, bg2, bi1, g_i, b_i, graph, p_h2h);

    // 6) effects = h2 @ Wi2 + bi2 (big tiles, 1728 CTAs)
    hgemm_big<<<dim3(HH/128, M_H2/128), blk, HG_SMEM_BIG>>>(
        p_h2h, p_Wi2h, bi2, effects, M_H2, HH, HH);
}

// round 13
// speedup vs baseline: 1.2420x; 1.0279x over previous
#include <cuda_runtime.h>
#include <cuda_fp16.h>
#include <cstdint>
#include <math.h>

// Problem dims
#define BB 32
#define VV 48
#define II 24
#define HH 768

#define M_ENC (BB*VV)        // 1536
#define M_HA  (BB*II)        // 768
#define M_H2  (BB*II*VV)     // 36864
#define NCAT  (3*HH)         // 2304

#define EFFECTS_ELEMS (M_H2*HH)
#define GRAPH_ELEMS   (BB*VV*VV)
#define ENC_ELEMS     (M_ENC*HH)

// -------- device scratch --------
__device__ __half g_varh[M_ENC*HH];
__device__ __half g_Wench[HH*HH];
__device__ float  g_pre[M_ENC*HH];
__device__ __half g_ench[M_ENC*HH];
__device__ __half g_Bcath[HH*NCAT];
__device__ float  g_hijb[M_ENC*NCAT];     // [1536][2304]: hi | hj | hb
__device__ __half g_inth[M_HA*HH];
__device__ __half g_Wi1h[HH*HH];          // Wi1[:H] only
__device__ float  g_ha[M_HA*HH];
__device__ __half g_Wi2h[HH*HH];
__device__ __half g_h2h[M_H2*HH];

// ======================= fp16 tensor-core GEMMs (mma.sync) =======================
#define AS 72     // A smem row stride (64+8) halves
#define BS 136    // B smem row stride (128+8) halves
#define STG_B (64*BS)

#define STG_A_BIG (128*AS)
#define STG_BIG   (STG_A_BIG + STG_B)
#define HG_SMEM_BIG (2*STG_BIG*2)       // 71680 bytes

#define STG_A_SML (64*AS)
#define STG_SML   (STG_A_SML + STG_B)
#define HG_SMEM_SML (2*STG_SML*2)       // 53248 bytes

__device__ __forceinline__ void cp16(unsigned int dst, const void* src) {
    asm volatile("cp.async.cg.shared.global [%0], [%1], 16;\n" :: "r"(dst), "l"(src));
}

// ---- warp-level compute for one 64-k chunk (32x64 warp tile) ----
__device__ __forceinline__ void mma_chunk(
    unsigned int aBuf, unsigned int bBuf, int wm, int wn, int lane,
    float acc[2][8][4])
{
    #pragma unroll
    for (int kk = 0; kk < 64; kk += 16) {
        unsigned int afr0[4], afr1[4];
        {
            int row = wm*32 + (lane & 15);
            int col = kk + ((lane >> 4) << 3);
            unsigned int addr = aBuf + (unsigned int)(row*AS + col)*2u;
            asm volatile("ldmatrix.sync.aligned.m8n8.x4.shared.b16 {%0,%1,%2,%3}, [%4];"
                : "=r"(afr0[0]), "=r"(afr0[1]), "=r"(afr0[2]), "=r"(afr0[3]) : "r"(addr));
        }
        {
            int row = wm*32 + 16 + (lane & 15);
            int col = kk + ((lane >> 4) << 3);
            unsigned int addr = aBuf + (unsigned int)(row*AS + col)*2u;
            asm volatile("ldmatrix.sync.aligned.m8n8.x4.shared.b16 {%0,%1,%2,%3}, [%4];"
                : "=r"(afr1[0]), "=r"(afr1[1]), "=r"(afr1[2]), "=r"(afr1[3]) : "r"(addr));
        }
        unsigned int bfr[8][2];
        #pragma unroll
        for (int nt2 = 0; nt2 < 4; nt2++) {
            int r = kk + (lane & 15);
            int col = wn*64 + nt2*16 + ((lane >> 4) << 3);
            unsigned int addr = bBuf + (unsigned int)(r*BS + col)*2u;
            asm volatile("ldmatrix.sync.aligned.m8n8.x4.trans.shared.b16 {%0,%1,%2,%3}, [%4];"
                : "=r"(bfr[2*nt2][0]), "=r"(bfr[2*nt2][1]),
                  "=r"(bfr[2*nt2+1][0]), "=r"(bfr[2*nt2+1][1]) : "r"(addr));
        }
        #pragma unroll
        for (int nt = 0; nt < 8; nt++) {
            asm volatile("mma.sync.aligned.m16n8k16.row.col.f32.f16.f16.f32 "
                "{%0,%1,%2,%3},{%4,%5,%6,%7},{%8,%9},{%0,%1,%2,%3};"
                : "+f"(acc[0][nt][0]), "+f"(acc[0][nt][1]), "+f"(acc[0][nt][2]), "+f"(acc[0][nt][3])
                : "r"(afr0[0]), "r"(afr0[1]), "r"(afr0[2]), "r"(afr0[3]),
                  "r"(bfr[nt][0]), "r"(bfr[nt][1]));
            asm volatile("mma.sync.aligned.m16n8k16.row.col.f32.f16.f16.f32 "
                "{%0,%1,%2,%3},{%4,%5,%6,%7},{%8,%9},{%0,%1,%2,%3};"
                : "+f"(acc[1][nt][0]), "+f"(acc[1][nt][1]), "+f"(acc[1][nt][2]), "+f"(acc[1][nt][3])
                : "r"(afr1[0]), "r"(afr1[1]), "r"(afr1[2]), "r"(afr1[3]),
                  "r"(bfr[nt][0]), "r"(bfr[nt][1]));
        }
    }
}

__device__ __forceinline__ void epilogue(
    float* __restrict__ C, const float* __restrict__ bias,
    int N, int bx, int byBase, int wm, int wn, int lane,
    float acc[2][8][4])
{
    float* Cb = C + (size_t)byBase * N + bx * 128;
    const float* biasb = bias ? (bias + bx * 128) : nullptr;
    #pragma unroll
    for (int mt = 0; mt < 2; mt++) {
        #pragma unroll
        for (int nt = 0; nt < 8; nt++) {
            int r0 = wm*32 + mt*16 + (lane >> 2);
            int c0 = wn*64 + nt*8 + (lane & 3)*2;
            float2 v0 = make_float2(acc[mt][nt][0], acc[mt][nt][1]);
            float2 v1 = make_float2(acc[mt][nt][2], acc[mt][nt][3]);
            if (biasb) {
                float2 bv = *(const float2*)(biasb + c0);
                v0.x += bv.x; v0.y += bv.y; v1.x += bv.x; v1.y += bv.y;
            }
            *(float2*)(Cb + (size_t)r0 * N + c0) = v0;
            *(float2*)(Cb + (size_t)(r0 + 8) * N + c0) = v1;
        }
    }
}

// ---------------- big variant: BM=128, 256 threads, 2-stage ----------------
__device__ __forceinline__ void load64_big(unsigned int aB, unsigned int bB,
    const __half* __restrict__ Ag, const __half* __restrict__ Bg,
    int k0, int K, int N, int tid)
{
    #pragma unroll
    for (int it = 0; it < 4; it++) {
        int q = tid + it*256;
        int row = q >> 3, cc = q & 7;
        cp16(aB + (unsigned int)(row*AS + cc*8)*2u, Ag + (size_t)row * K + k0 + cc*8);
    }
    #pragma unroll
    for (int it = 0; it < 4; it++) {
        int q = tid + it*256;
        int row = q >> 4, cc = q & 15;
        cp16(bB + (unsigned int)(row*BS + cc*8)*2u, Bg + (size_t)(k0 + row) * N + cc*8);
    }
}

__global__ __launch_bounds__(256) void hgemm_big(
    const __half* __restrict__ A0, const __half* __restrict__ B0,
    const float* __restrict__ bias, float* __restrict__ C,
    int M, int N, int K)
{
    extern __shared__ __align__(16) __half sm[];
    const int bx = blockIdx.x, by = blockIdx.y;
    const int tid = threadIdx.x;
    const int lane = tid & 31, w = tid >> 5;
    const int wm = w & 3, wn = w >> 2;

    const unsigned int sbase = (unsigned int)__cvta_generic_to_shared(sm);
    const unsigned int aS[2] = {sbase,                           sbase + (unsigned)STG_BIG*2u};
    const unsigned int bS[2] = {sbase + (unsigned)STG_A_BIG*2u,  sbase + (unsigned)(STG_BIG + STG_A_BIG)*2u};

    const int total = K >> 6;
    const __half* Ag = A0 + (size_t)by*128*K;
    const __half* Bg = B0 + bx*128;

    float acc[2][8][4];
    #pragma unroll
    for (int mt = 0; mt < 2; mt++)
        #pragma unroll
        for (int nt = 0; nt < 8; nt++)
            #pragma unroll
            for (int q = 0; q < 4; q++) acc[mt][nt][q] = 0.f;

    load64_big(aS[0], bS[0], Ag, Bg, 0, K, N, tid);
    asm volatile("cp.async.commit_group;\n" ::);

    for (int c = 0; c < total; c++) {
        const int buf = c & 1;
        if (c + 1 < total) {
            load64_big(aS[buf^1], bS[buf^1], Ag, Bg, (c+1)*64, K, N, tid);
            asm volatile("cp.async.commit_group;\n" ::);
            asm volatile("cp.async.wait_group 1;\n" ::);
        } else {
            asm volatile("cp.async.wait_group 0;\n" ::);
        }
        __syncthreads();
        mma_chunk(aS[buf], bS[buf], wm, wn, lane, acc);
        __syncthreads();
    }

    epilogue(C, bias, N, bx, by*128, wm, wn, lane, acc);
}

// ---------------- small variant core (BM=64, 128 threads, 2-stage) ----------------
__device__ __forceinline__ void load64_sml(unsigned int aB, unsigned int bB,
    const __half* __restrict__ Ag, const __half* __restrict__ Bg,
    int k0, int K, int N, int tid)
{
    #pragma unroll
    for (int it = 0; it < 4; it++) {
        int q = tid + it*128;
        int row = q >> 3, cc = q & 7;
        cp16(aB + (unsigned int)(row*AS + cc*8)*2u, Ag + (size_t)row * K + k0 + cc*8);
    }
    #pragma unroll
    for (int it = 0; it < 8; it++) {
        int q = tid + it*128;
        int row = q >> 4, cc = q & 15;
        cp16(bB + (unsigned int)(row*BS + cc*8)*2u, Bg + (size_t)(k0 + row) * N + cc*8);
    }
}

__device__ __forceinline__ void sml_body(
    const __half* A0, const __half* B0,
    const float* bias, float* C, int N, int K, int by, int bx)
{
    extern __shared__ __align__(16) __half sm[];
    const int tid = threadIdx.x;
    const int lane = tid & 31, w = tid >> 5;
    const int wm = w & 1, wn = w >> 1;

    const unsigned int sbase = (unsigned int)__cvta_generic_to_shared(sm);
    const unsigned int aS[2] = {sbase,                           sbase + (unsigned)STG_SML*2u};
    const unsigned int bS[2] = {sbase + (unsigned)STG_A_SML*2u,  sbase + (unsigned)(STG_SML + STG_A_SML)*2u};

    const int total = K >> 6;
    const __half* Ag = A0 + (size_t)by*64*K;
    const __half* Bg = B0 + bx*128;

    float acc[2][8][4];
    #pragma unroll
    for (int mt = 0; mt < 2; mt++)
        #pragma unroll
        for (int nt = 0; nt < 8; nt++)
            #pragma unroll
            for (int q = 0; q < 4; q++) acc[mt][nt][q] = 0.f;

    load64_sml(aS[0], bS[0], Ag, Bg, 0, K, N, tid);
    asm volatile("cp.async.commit_group;\n" ::);

    for (int c = 0; c < total; c++) {
        const int buf = c & 1;
        if (c + 1 < total) {
            load64_sml(aS[buf^1], bS[buf^1], Ag, Bg, (c+1)*64, K, N, tid);
            asm volatile("cp.async.commit_group;\n" ::);
            asm volatile("cp.async.wait_group 1;\n" ::);
        } else {
            asm volatile("cp.async.wait_group 0;\n" ::);
        }
        __syncthreads();
        mma_chunk(aS[buf], bS[buf], wm, wn, lane, acc);
        __syncthreads();
    }

    epilogue(C, bias, N, bx, by*64, wm, wn, lane, acc);
}

__global__ __launch_bounds__(128, 4) void hgemm_sml(
    const __half* __restrict__ A0, const __half* __restrict__ B0,
    const float* __restrict__ bias, float* __restrict__ C,
    int M, int N, int K)
{
    sml_body(A0, B0, bias, C, N, K, blockIdx.y, blockIdx.x);
}

__global__ __launch_bounds__(128, 4) void hgemm_sml_b2(
    const __half* __restrict__ A0a, const __half* __restrict__ B0a,
    const float* __restrict__ biasa, float* __restrict__ Ca, int tilesA,
    const __half* __restrict__ A0b, const __half* __restrict__ B0b,
    const float* __restrict__ biasb, float* __restrict__ Cb,
    int N, int K)
{
    const int nbx = N / 128;
    const int tile = blockIdx.x / nbx;
    const int bx   = blockIdx.x % nbx;
    if (tile < tilesA) {
        sml_body(A0a, B0a, biasa, Ca, N, K, tile, bx);
    } else {
        sml_body(A0b, B0b, biasb, Cb, N, K, tile - tilesA, bx);
    }
}

// ================= merged prep (ONE launch, float4-vectorized) =================
#define NW (HH*HH)
#define N_VAR (M_ENC*HH)
#define N_INT (M_HA*HH)
#define PREP_TOTAL4 ((N_VAR + N_INT + 3*NW + HH*NCAT)/4)

__device__ __forceinline__ void cvt4_store(const float4 v, __half* dst) {
    __half2 lo = __floats2half2_rn(v.x, v.y);
    __half2 hi = __floats2half2_rn(v.z, v.w);
    uint2 u;
    u.x = *(unsigned int*)&lo;
    u.y = *(unsigned int*)&hi;
    *(uint2*)dst = u;
}

__global__ void prep_all(
    const float* __restrict__ variables, const float* __restrict__ interventions,
    const float* __restrict__ W_enc, const float* __restrict__ Wi1,
    const float* __restrict__ Wi2,   const float* __restrict__ Wg1,
    __half* __restrict__ varh, __half* __restrict__ inth,
    __half* __restrict__ Wench, __half* __restrict__ Wi1h,
    __half* __restrict__ Wi2h,  __half* __restrict__ Bcath)
{
    int q = blockIdx.x * 256 + threadIdx.x;
    int i = q * 4;
    if (i < N_VAR) { cvt4_store(*(const float4*)(variables + i), varh + i); return; }
    i -= N_VAR;
    if (i < N_INT) { cvt4_store(*(const float4*)(interventions + i), inth + i); return; }
    i -= N_INT;
    if (i < NW) { cvt4_store(*(const float4*)(W_enc + i), Wench + i); return; }
    i -= NW;
    if (i < NW) { cvt4_store(*(const float4*)(Wi1 + i), Wi1h + i); return; }
    i -= NW;
    if (i < NW) { cvt4_store(*(const float4*)(Wi2 + i), Wi2h + i); return; }
    i -= NW;
    if (i < HH * NCAT) {
        int r = i / NCAT, c = i % NCAT;   // c aligned to 4; segment boundaries are multiples of 4
        float4 v;
        if (c < HH)            v = *(const float4*)(Wg1 + (size_t)r * HH + c);
        else if (c < 2 * HH)   v = *(const float4*)(Wg1 + (size_t)(HH + r) * HH + (c - HH));
        else                   v = *(const float4*)(Wi1 + (size_t)(HH + r) * HH + (c - 2 * HH));
        cvt4_store(v, Bcath + i);
    }
}

// ================= reductions (2-barrier, bit-identical order) =================
__device__ __forceinline__ float blockSum256(float v) {
    #pragma unroll
    for (int o = 16; o > 0; o >>= 1) v += __shfl_down_sync(0xffffffffu, v, o);
    __shared__ float sh[8];
    int lane = threadIdx.x & 31, w = threadIdx.x >> 5;
    __syncthreads();                    // protect WAR vs previous call's reads
    if (lane == 0) sh[w] = v;
    __syncthreads();
    float t = 0.f;
    #pragma unroll
    for (int k = 0; k < 8; k++) t += sh[k];
    return t;
}

__device__ __forceinline__ float2 blockSum2(float a, float b) {
    #pragma unroll
    for (int o = 16; o > 0; o >>= 1) {
        a += __shfl_down_sync(0xffffffffu, a, o);
        b += __shfl_down_sync(0xffffffffu, b, o);
    }
    __shared__ float2 sh2[8];
    int lane = threadIdx.x & 31, w = threadIdx.x >> 5;
    __syncthreads();
    if (lane == 0) sh2[w] = make_float2(a, b);
    __syncthreads();
    float ta = 0.f, tb = 0.f;
    #pragma unroll
    for (int k = 0; k < 8; k++) { ta += sh2[k].x; tb += sh2[k].y; }
    return make_float2(ta, tb);
}

__global__ __launch_bounds__(256) void ln_relu_kernel(
    const float* __restrict__ X, const float* __restrict__ gamma,
    const float* __restrict__ beta, float* __restrict__ Y,
    __half* __restrict__ Yh)
{
    const int row = blockIdx.x;
    const float* x = X + (size_t)row * HH;
    const int t = threadIdx.x;
    float x0 = x[t], x1 = x[t + 256], x2 = x[t + 512];
    float2 sq = blockSum2(x0 + x1 + x2, x0*x0 + x1*x1 + x2*x2);
    float mu = sq.x * (1.f / HH);
    float var = sq.y * (1.f / HH) - mu * mu;
    float inv = rsqrtf(var + 1e-5f);
    float y0 = fmaxf((x0 - mu) * inv * gamma[t]       + beta[t],       0.f);
    float y1 = fmaxf((x1 - mu) * inv * gamma[t + 256] + beta[t + 256], 0.f);
    float y2 = fmaxf((x2 - mu) * inv * gamma[t + 512] + beta[t + 512], 0.f);
    size_t o = (size_t)row * HH;
    Y[o + t] = y0; Y[o + t + 256] = y1; Y[o + t + 512] = y2;
    Yh[o + t]       = __float2half_rn(y0);
    Yh[o + t + 256] = __float2half_rn(y1);
    Yh[o + t + 512] = __float2half_rn(y2);
}

#define JCH 12   // j-chunk size (48/4)

// merged graph + h2: grid (VV, BB, 8); z<4 -> graph jc=z; z>=4 -> h2 jc=z-4 (x<II only)
__global__ __launch_bounds__(256) void pairwise_kernel(
    const float* __restrict__ hijb, const float* __restrict__ ha,
    const float* __restrict__ bg1, const float* __restrict__ g_g,
    const float* __restrict__ b_g, const float* __restrict__ Wg2,
    const float* __restrict__ bg2,
    const float* __restrict__ bi1, const float* __restrict__ g_i,
    const float* __restrict__ b_i,
    float* __restrict__ graph, __half* __restrict__ h2out)
{
    const int b = blockIdx.y;
    const int t = threadIdx.x;
    const int z = blockIdx.z;

    if (z < 4) {
        const int i = blockIdx.x, jc = z;
        const float* xi = hijb + (size_t)(b * VV + i) * NCAT;
        const float a0 = xi[t]       + bg1[t];
        const float a1 = xi[t + 256] + bg1[t + 256];
        const float a2 = xi[t + 512] + bg1[t + 512];
        const float gg0 = g_g[t], gg1 = g_g[t+256], gg2 = g_g[t+512];
        const float bb0 = b_g[t],  bb1 = b_g[t+256],  bb2 = b_g[t+512];
        const float w0 = Wg2[t], w1 = Wg2[t+256], w9 = Wg2[t+512];
        const float b20 = bg2[0];
        float* orow = graph + (size_t)(b * VV + i) * VV;

        for (int j = jc*JCH; j < jc*JCH + JCH; j++) {
            const float* xj = hijb + (size_t)(b * VV + j) * NCAT + HH;
            float x0 = a0 + xj[t];
            float x1 = a1 + xj[t + 256];
            float x2 = a2 + xj[t + 512];
            float2 sq = blockSum2(x0 + x1 + x2, x0*x0 + x1*x1 + x2*x2);
            float mu = sq.x * (1.f / HH);
            float var = sq.y * (1.f / HH) - mu * mu;
            float inv = rsqrtf(var + 1e-5f);
            float y0 = fmaxf((x0 - mu) * inv * gg0 + bb0, 0.f);
            float y1 = fmaxf((x1 - mu) * inv * gg1 + bb1, 0.f);
            float y2 = fmaxf((x2 - mu) * inv * gg2 + bb2, 0.f);
            float d = blockSum256(y0 * w0 + y1 * w1 + y2 * w9);
            if (t == 0)
                orow[j] = (i == j) ? 0.f : 1.f / (1.f + expf(-(d + b20)));
        }
    } else {
        const int i = blockIdx.x;
        if (i >= II) return;
        const int jc = z - 4;
        const float* xa = ha + (size_t)(b * II + i) * HH;
        const float a0 = xa[t]       + bi1[t];
        const float a1 = xa[t + 256] + bi1[t + 256];
        const float a2 = xa[t + 512] + bi1[t + 512];
        const float gg0 = g_i[t], gg1 = g_i[t+256], gg2 = g_i[t+512];
        const float bb0 = b_i[t],  bb1 = b_i[t+256],  bb2 = b_i[t+512];
        __half* yb = h2out + (size_t)(b * II + i) * VV * HH;

        for (int j = jc*JCH; j < jc*JCH + JCH; j++) {
            const float* xb = hijb + (size_t)(b * VV + j) * NCAT + 2 * HH;
            float x0 = a0 + xb[t];
            float x1 = a1 + xb[t + 256];
            float x2 = a2 + xb[t + 512];
            float2 sq = blockSum2(x0 + x1 + x2, x0*x0 + x1*x1 + x2*x2);
            float mu = sq.x * (1.f / HH);
            float var = sq.y * (1.f / HH) - mu * mu;
            float inv = rsqrtf(var + 1e-5f);
            __half* y = yb + (size_t)j * HH;
            y[t]       = __float2half_rn(fmaxf((x0 - mu) * inv * gg0 + bb0, 0.f));
            y[t + 256] = __float2half_rn(fmaxf((x1 - mu) * inv * gg1 + bb1, 0.f));
            y[t + 512] = __float2half_rn(fmaxf((x2 - mu) * inv * gg2 + bb2, 0.f));
        }
    }
}

extern "C" void kernel_launch(void* const* d_in, const int* in_sizes, int n_in,
                              void* d_out, int out_size) {
    const float* variables     = (const float*)d_in[0];
    const float* interventions = (const float*)d_in[1];
    const float* W_enc  = (const float*)d_in[2];
    const float* b_enc  = (const float*)d_in[3];
    const float* g_enc  = (const float*)d_in[4];
    const float* be_enc = (const float*)d_in[5];
    const float* Wg1    = (const float*)d_in[6];
    const float* bg1    = (const float*)d_in[7];
    const float* g_g    = (const float*)d_in[8];
    const float* b_g    = (const float*)d_in[9];
    const float* Wg2    = (const float*)d_in[10];
    const float* bg2    = (const float*)d_in[11];
    const float* Wi1    = (const float*)d_in[12];
    const float* bi1    = (const float*)d_in[13];
    const float* g_i    = (const float*)d_in[14];
    const float* b_i    = (const float*)d_in[15];
    const float* Wi2    = (const float*)d_in[16];
    const float* bi2    = (const float*)d_in[17];

    float* effects = (float*)d_out;
    float* graph   = effects + EFFECTS_ELEMS;
    float* enc     = graph + GRAPH_ELEMS;

    __half *p_varh, *p_Wench, *p_ench, *p_Bcath, *p_inth, *p_Wi1h, *p_Wi2h, *p_h2h;
    float *p_pre, *p_hijb, *p_ha;
    cudaGetSymbolAddress((void**)&p_varh,  g_varh);
    cudaGetSymbolAddress((void**)&p_Wench, g_Wench);
    cudaGetSymbolAddress((void**)&p_pre,   g_pre);
    cudaGetSymbolAddress((void**)&p_ench,  g_ench);
    cudaGetSymbolAddress((void**)&p_Bcath, g_Bcath);
    cudaGetSymbolAddress((void**)&p_hijb,  g_hijb);
    cudaGetSymbolAddress((void**)&p_inth,  g_inth);
    cudaGetSymbolAddress((void**)&p_Wi1h,  g_Wi1h);
    cudaGetSymbolAddress((void**)&p_ha,    g_ha);
    cudaGetSymbolAddress((void**)&p_Wi2h,  g_Wi2h);
    cudaGetSymbolAddress((void**)&p_h2h,   g_h2h);

    cudaFuncSetAttribute(hgemm_big,    cudaFuncAttributeMaxDynamicSharedMemorySize, HG_SMEM_BIG);
    cudaFuncSetAttribute(hgemm_sml,    cudaFuncAttributeMaxDynamicSharedMemorySize, HG_SMEM_SML);
    cudaFuncSetAttribute(hgemm_sml_b2, cudaFuncAttributeMaxDynamicSharedMemorySize, HG_SMEM_SML);

    dim3 blk(256);
    dim3 blk128(128);

    // 1) all converts in one vectorized launch
    prep_all<<<(PREP_TOTAL4 + 255)/256, blk>>>(
        variables, interventions, W_enc, Wi1, Wi2, Wg1,
        p_varh, p_inth, p_Wench, p_Wi1h, p_Wi2h, p_Bcath);

    // 2) pre + ha batched in one launch (216 CTAs, single pass)
    hgemm_sml_b2<<<dim3((M_ENC/64 + M_HA/64) * (HH/128)), blk128, HG_SMEM_SML>>>(
        p_varh, p_Wench, b_enc, p_pre, M_ENC/64,
        p_inth, p_Wi1h, nullptr, p_ha,
        HH, HH);

    // 3) enc = relu(LN(pre))
    ln_relu_kernel<<<M_ENC, blk>>>(p_pre, g_enc, be_enc, enc, p_ench);

    // 4) hijb = enc @ [Wg1a|Wg1b|Wi1b]  (432 CTAs, single pass)
    hgemm_sml<<<dim3(NCAT/128, M_ENC/64), blk128, HG_SMEM_SML>>>(
        p_ench, p_Bcath, nullptr, p_hijb, M_ENC, NCAT, HH);

    // 5) graph + h2 merged
    pairwise_kernel<<<dim3(VV, BB, 8), blk>>>(
        p_hijb, p_ha, bg1, g_g, b_g, Wg2, bg2, bi1, g_i, b_i, graph, p_h2h);

    // 6) effects = h2 @ Wi2 + bi2 (big tiles, 1728 CTAs)
    hgemm_big<<<dim3(HH/128, M_H2/128), blk, HG_SMEM_BIG>>>(
        p_h2h, p_Wi2h, bi2, effects, M_H2, HH, HH);
}

// round 14
// speedup vs baseline: 1.5001x; 1.2078x over previous
#include <cuda_runtime.h>
#include <cuda_fp16.h>
#include <cstdint>
#include <math.h>

// Problem dims
#define BB 32
#define VV 48
#define II 24
#define HH 768

#define M_ENC (BB*VV)        // 1536
#define M_HA  (BB*II)        // 768
#define M_H2  (BB*II*VV)     // 36864
#define NCAT  (3*HH)         // 2304

#define EFFECTS_ELEMS (M_H2*HH)
#define GRAPH_ELEMS   (BB*VV*VV)
#define ENC_ELEMS     (M_ENC*HH)

// -------- device scratch --------
__device__ __half g_varh[M_ENC*HH];
__device__ __half g_Wench[HH*HH];
__device__ float  g_pre[M_ENC*HH];
__device__ __half g_ench[M_ENC*HH];
__device__ __half g_Bcath[HH*NCAT];
__device__ float  g_hijb[M_ENC*NCAT];     // [1536][2304]: hi | hj | hb
__device__ __half g_inth[M_HA*HH];
__device__ __half g_Wi1h[HH*HH];          // Wi1[:H] only
__device__ float  g_ha[M_HA*HH];
__device__ __half g_Wi2h[HH*HH];
__device__ __half g_h2h[M_H2*HH];

// ======================= fp16 tensor-core GEMMs (mma.sync) =======================
#define AS 72     // A smem row stride (64+8) halves
#define BS 136    // B smem row stride (128+8) halves
#define STG_B (64*BS)

#define STG_A_BIG (128*AS)
#define STG_BIG   (STG_A_BIG + STG_B)
#define HG_SMEM_BIG (2*STG_BIG*2)       // 71680 bytes

#define STG_A_SML (64*AS)
#define STG_SML   (STG_A_SML + STG_B)
#define HG_SMEM_SML (2*STG_SML*2)       // 53248 bytes

__device__ __forceinline__ void cp16(unsigned int dst, const void* src) {
    asm volatile("cp.async.cg.shared.global [%0], [%1], 16;\n" :: "r"(dst), "l"(src));
}

// ---- warp-level compute for one 64-k chunk (32x64 warp tile) ----
__device__ __forceinline__ void mma_chunk(
    unsigned int aBuf, unsigned int bBuf, int wm, int wn, int lane,
    float acc[2][8][4])
{
    #pragma unroll
    for (int kk = 0; kk < 64; kk += 16) {
        unsigned int afr0[4], afr1[4];
        {
            int row = wm*32 + (lane & 15);
            int col = kk + ((lane >> 4) << 3);
            unsigned int addr = aBuf + (unsigned int)(row*AS + col)*2u;
            asm volatile("ldmatrix.sync.aligned.m8n8.x4.shared.b16 {%0,%1,%2,%3}, [%4];"
                : "=r"(afr0[0]), "=r"(afr0[1]), "=r"(afr0[2]), "=r"(afr0[3]) : "r"(addr));
        }
        {
            int row = wm*32 + 16 + (lane & 15);
            int col = kk + ((lane >> 4) << 3);
            unsigned int addr = aBuf + (unsigned int)(row*AS + col)*2u;
            asm volatile("ldmatrix.sync.aligned.m8n8.x4.shared.b16 {%0,%1,%2,%3}, [%4];"
                : "=r"(afr1[0]), "=r"(afr1[1]), "=r"(afr1[2]), "=r"(afr1[3]) : "r"(addr));
        }
        unsigned int bfr[8][2];
        #pragma unroll
        for (int nt2 = 0; nt2 < 4; nt2++) {
            int r = kk + (lane & 15);
            int col = wn*64 + nt2*16 + ((lane >> 4) << 3);
            unsigned int addr = bBuf + (unsigned int)(r*BS + col)*2u;
            asm volatile("ldmatrix.sync.aligned.m8n8.x4.trans.shared.b16 {%0,%1,%2,%3}, [%4];"
                : "=r"(bfr[2*nt2][0]), "=r"(bfr[2*nt2][1]),
                  "=r"(bfr[2*nt2+1][0]), "=r"(bfr[2*nt2+1][1]) : "r"(addr));
        }
        #pragma unroll
        for (int nt = 0; nt < 8; nt++) {
            asm volatile("mma.sync.aligned.m16n8k16.row.col.f32.f16.f16.f32 "
                "{%0,%1,%2,%3},{%4,%5,%6,%7},{%8,%9},{%0,%1,%2,%3};"
                : "+f"(acc[0][nt][0]), "+f"(acc[0][nt][1]), "+f"(acc[0][nt][2]), "+f"(acc[0][nt][3])
                : "r"(afr0[0]), "r"(afr0[1]), "r"(afr0[2]), "r"(afr0[3]),
                  "r"(bfr[nt][0]), "r"(bfr[nt][1]));
            asm volatile("mma.sync.aligned.m16n8k16.row.col.f32.f16.f16.f32 "
                "{%0,%1,%2,%3},{%4,%5,%6,%7},{%8,%9},{%0,%1,%2,%3};"
                : "+f"(acc[1][nt][0]), "+f"(acc[1][nt][1]), "+f"(acc[1][nt][2]), "+f"(acc[1][nt][3])
                : "r"(afr1[0]), "r"(afr1[1]), "r"(afr1[2]), "r"(afr1[3]),
                  "r"(bfr[nt][0]), "r"(bfr[nt][1]));
        }
    }
}

__device__ __forceinline__ void epilogue(
    float* __restrict__ C, const float* __restrict__ bias,
    int N, int bx, int byBase, int wm, int wn, int lane,
    float acc[2][8][4])
{
    float* Cb = C + (size_t)byBase * N + bx * 128;
    const float* biasb = bias ? (bias + bx * 128) : nullptr;
    #pragma unroll
    for (int mt = 0; mt < 2; mt++) {
        #pragma unroll
        for (int nt = 0; nt < 8; nt++) {
            int r0 = wm*32 + mt*16 + (lane >> 2);
            int c0 = wn*64 + nt*8 + (lane & 3)*2;
            float2 v0 = make_float2(acc[mt][nt][0], acc[mt][nt][1]);
            float2 v1 = make_float2(acc[mt][nt][2], acc[mt][nt][3]);
            if (biasb) {
                float2 bv = *(const float2*)(biasb + c0);
                v0.x += bv.x; v0.y += bv.y; v1.x += bv.x; v1.y += bv.y;
            }
            *(float2*)(Cb + (size_t)r0 * N + c0) = v0;
            *(float2*)(Cb + (size_t)(r0 + 8) * N + c0) = v1;
        }
    }
}

// ---------------- big variant: BM=128, 256 threads, 2-stage ----------------
__device__ __forceinline__ void load64_big(unsigned int aB, unsigned int bB,
    const __half* __restrict__ Ag, const __half* __restrict__ Bg,
    int k0, int K, int N, int tid)
{
    #pragma unroll
    for (int it = 0; it < 4; it++) {
        int q = tid + it*256;
        int row = q >> 3, cc = q & 7;
        cp16(aB + (unsigned int)(row*AS + cc*8)*2u, Ag + (size_t)row * K + k0 + cc*8);
    }
    #pragma unroll
    for (int it = 0; it < 4; it++) {
        int q = tid + it*256;
        int row = q >> 4, cc = q & 15;
        cp16(bB + (unsigned int)(row*BS + cc*8)*2u, Bg + (size_t)(k0 + row) * N + cc*8);
    }
}

__global__ __launch_bounds__(256) void hgemm_big(
    const __half* __restrict__ A0, const __half* __restrict__ B0,
    const float* __restrict__ bias, float* __restrict__ C,
    int M, int N, int K)
{
    extern __shared__ __align__(16) __half sm[];
    const int bx = blockIdx.x, by = blockIdx.y;
    const int tid = threadIdx.x;
    const int lane = tid & 31, w = tid >> 5;
    const int wm = w & 3, wn = w >> 2;

    const unsigned int sbase = (unsigned int)__cvta_generic_to_shared(sm);
    const unsigned int aS[2] = {sbase,                           sbase + (unsigned)STG_BIG*2u};
    const unsigned int bS[2] = {sbase + (unsigned)STG_A_BIG*2u,  sbase + (unsigned)(STG_BIG + STG_A_BIG)*2u};

    const int total = K >> 6;
    const __half* Ag = A0 + (size_t)by*128*K;
    const __half* Bg = B0 + bx*128;

    float acc[2][8][4];
    #pragma unroll
    for (int mt = 0; mt < 2; mt++)
        #pragma unroll
        for (int nt = 0; nt < 8; nt++)
            #pragma unroll
            for (int q = 0; q < 4; q++) acc[mt][nt][q] = 0.f;

    load64_big(aS[0], bS[0], Ag, Bg, 0, K, N, tid);
    asm volatile("cp.async.commit_group;\n" ::);

    for (int c = 0; c < total; c++) {
        const int buf = c & 1;
        if (c + 1 < total) {
            load64_big(aS[buf^1], bS[buf^1], Ag, Bg, (c+1)*64, K, N, tid);
            asm volatile("cp.async.commit_group;\n" ::);
            asm volatile("cp.async.wait_group 1;\n" ::);
        } else {
            asm volatile("cp.async.wait_group 0;\n" ::);
        }
        __syncthreads();
        mma_chunk(aS[buf], bS[buf], wm, wn, lane, acc);
        __syncthreads();
    }

    epilogue(C, bias, N, bx, by*128, wm, wn, lane, acc);
}

// ---------------- small variant core (BM=64, 128 threads, 2-stage) ----------------
__device__ __forceinline__ void load64_sml(unsigned int aB, unsigned int bB,
    const __half* __restrict__ Ag, const __half* __restrict__ Bg,
    int k0, int K, int N, int tid)
{
    #pragma unroll
    for (int it = 0; it < 4; it++) {
        int q = tid + it*128;
        int row = q >> 3, cc = q & 7;
        cp16(aB + (unsigned int)(row*AS + cc*8)*2u, Ag + (size_t)row * K + k0 + cc*8);
    }
    #pragma unroll
    for (int it = 0; it < 8; it++) {
        int q = tid + it*128;
        int row = q >> 4, cc = q & 15;
        cp16(bB + (unsigned int)(row*BS + cc*8)*2u, Bg + (size_t)(k0 + row) * N + cc*8);
    }
}

__device__ __forceinline__ void sml_body(
    const __half* A0, const __half* B0,
    const float* bias, float* C, int N, int K, int by, int bx)
{
    extern __shared__ __align__(16) __half sm[];
    const int tid = threadIdx.x;
    const int lane = tid & 31, w = tid >> 5;
    const int wm = w & 1, wn = w >> 1;

    const unsigned int sbase = (unsigned int)__cvta_generic_to_shared(sm);
    const unsigned int aS[2] = {sbase,                           sbase + (unsigned)STG_SML*2u};
    const unsigned int bS[2] = {sbase + (unsigned)STG_A_SML*2u,  sbase + (unsigned)(STG_SML + STG_A_SML)*2u};

    const int total = K >> 6;
    const __half* Ag = A0 + (size_t)by*64*K;
    const __half* Bg = B0 + bx*128;

    float acc[2][8][4];
    #pragma unroll
    for (int mt = 0; mt < 2; mt++)
        #pragma unroll
        for (int nt = 0; nt < 8; nt++)
            #pragma unroll
            for (int q = 0; q < 4; q++) acc[mt][nt][q] = 0.f;

    load64_sml(aS[0], bS[0], Ag, Bg, 0, K, N, tid);
    asm volatile("cp.async.commit_group;\n" ::);

    for (int c = 0; c < total; c++) {
        const int buf = c & 1;
        if (c + 1 < total) {
            load64_sml(aS[buf^1], bS[buf^1], Ag, Bg, (c+1)*64, K, N, tid);
            asm volatile("cp.async.commit_group;\n" ::);
            asm volatile("cp.async.wait_group 1;\n" ::);
        } else {
            asm volatile("cp.async.wait_group 0;\n" ::);
        }
        __syncthreads();
        mma_chunk(aS[buf], bS[buf], wm, wn, lane, acc);
        __syncthreads();
    }

    epilogue(C, bias, N, bx, by*64, wm, wn, lane, acc);
}

__global__ __launch_bounds__(128, 4) void hgemm_sml(
    const __half* __restrict__ A0, const __half* __restrict__ B0,
    const float* __restrict__ bias, float* __restrict__ C,
    int M, int N, int K)
{
    sml_body(A0, B0, bias, C, N, K, blockIdx.y, blockIdx.x);
}

__global__ __launch_bounds__(128, 4) void hgemm_sml_b2(
    const __half* __restrict__ A0a, const __half* __restrict__ B0a,
    const float* __restrict__ biasa, float* __restrict__ Ca, int tilesA,
    const __half* __restrict__ A0b, const __half* __restrict__ B0b,
    const float* __restrict__ biasb, float* __restrict__ Cb,
    int N, int K)
{
    const int nbx = N / 128;
    const int tile = blockIdx.x / nbx;
    const int bx   = blockIdx.x % nbx;
    if (tile < tilesA) {
        sml_body(A0a, B0a, biasa, Ca, N, K, tile, bx);
    } else {
        sml_body(A0b, B0b, biasb, Cb, N, K, tile - tilesA, bx);
    }
}

// ================= merged prep (ONE launch, float4-vectorized) =================
#define NW (HH*HH)
#define N_VAR (M_ENC*HH)
#define N_INT (M_HA*HH)
#define PREP_TOTAL4 ((N_VAR + N_INT + 3*NW + HH*NCAT)/4)

__device__ __forceinline__ void cvt4_store(const float4 v, __half* dst) {
    __half2 lo = __floats2half2_rn(v.x, v.y);
    __half2 hi = __floats2half2_rn(v.z, v.w);
    uint2 u;
    u.x = *(unsigned int*)&lo;
    u.y = *(unsigned int*)&hi;
    *(uint2*)dst = u;
}

__global__ void prep_all(
    const float* __restrict__ variables, const float* __restrict__ interventions,
    const float* __restrict__ W_enc, const float* __restrict__ Wi1,
    const float* __restrict__ Wi2,   const float* __restrict__ Wg1,
    __half* __restrict__ varh, __half* __restrict__ inth,
    __half* __restrict__ Wench, __half* __restrict__ Wi1h,
    __half* __restrict__ Wi2h,  __half* __restrict__ Bcath)
{
    int q = blockIdx.x * 256 + threadIdx.x;
    int i = q * 4;
    if (i < N_VAR) { cvt4_store(*(const float4*)(variables + i), varh + i); return; }
    i -= N_VAR;
    if (i < N_INT) { cvt4_store(*(const float4*)(interventions + i), inth + i); return; }
    i -= N_INT;
    if (i < NW) { cvt4_store(*(const float4*)(W_enc + i), Wench + i); return; }
    i -= NW;
    if (i < NW) { cvt4_store(*(const float4*)(Wi1 + i), Wi1h + i); return; }
    i -= NW;
    if (i < NW) { cvt4_store(*(const float4*)(Wi2 + i), Wi2h + i); return; }
    i -= NW;
    if (i < HH * NCAT) {
        int r = i / NCAT, c = i % NCAT;
        float4 v;
        if (c < HH)            v = *(const float4*)(Wg1 + (size_t)r * HH + c);
        else if (c < 2 * HH)   v = *(const float4*)(Wg1 + (size_t)(HH + r) * HH + (c - HH));
        else                   v = *(const float4*)(Wi1 + (size_t)(HH + r) * HH + (c - 2 * HH));
        cvt4_store(v, Bcath + i);
    }
}

// ================= reductions (2-barrier) =================
__device__ __forceinline__ float2 blockSum2(float a, float b) {
    #pragma unroll
    for (int o = 16; o > 0; o >>= 1) {
        a += __shfl_down_sync(0xffffffffu, a, o);
        b += __shfl_down_sync(0xffffffffu, b, o);
    }
    __shared__ float2 sh2[8];
    int lane = threadIdx.x & 31, w = threadIdx.x >> 5;
    __syncthreads();
    if (lane == 0) sh2[w] = make_float2(a, b);
    __syncthreads();
    float ta = 0.f, tb = 0.f;
    #pragma unroll
    for (int k = 0; k < 8; k++) { ta += sh2[k].x; tb += sh2[k].y; }
    return make_float2(ta, tb);
}

__global__ __launch_bounds__(256) void ln_relu_kernel(
    const float* __restrict__ X, const float* __restrict__ gamma,
    const float* __restrict__ beta, float* __restrict__ Y,
    __half* __restrict__ Yh)
{
    const int row = blockIdx.x;
    const float* x = X + (size_t)row * HH;
    const int t = threadIdx.x;
    float x0 = x[t], x1 = x[t + 256], x2 = x[t + 512];
    float2 sq = blockSum2(x0 + x1 + x2, x0*x0 + x1*x1 + x2*x2);
    float mu = sq.x * (1.f / HH);
    float var = sq.y * (1.f / HH) - mu * mu;
    float inv = rsqrtf(var + 1e-5f);
    float y0 = fmaxf((x0 - mu) * inv * gamma[t]       + beta[t],       0.f);
    float y1 = fmaxf((x1 - mu) * inv * gamma[t + 256] + beta[t + 256], 0.f);
    float y2 = fmaxf((x2 - mu) * inv * gamma[t + 512] + beta[t + 512], 0.f);
    size_t o = (size_t)row * HH;
    Y[o + t] = y0; Y[o + t + 256] = y1; Y[o + t + 512] = y2;
    Yh[o + t]       = __float2half_rn(y0);
    Yh[o + t + 256] = __float2half_rn(y1);
    Yh[o + t + 512] = __float2half_rn(y2);
}

// ================= pairwise: warp-per-row, barrier-free =================
// grid (VV, BB, 2), 256 threads (8 warps). z=0: graph (warp w handles j=w+8q, q<6).
// z=1: h2 (blocks with i>=II exit). 24 elems per lane (idx = lane + 32k).
__global__ __launch_bounds__(256) void pairwise_warp(
    const float* __restrict__ hijb, const float* __restrict__ ha,
    const float* __restrict__ bg1, const float* __restrict__ g_g,
    const float* __restrict__ b_g, const float* __restrict__ Wg2,
    const float* __restrict__ bg2,
    const float* __restrict__ bi1, const float* __restrict__ g_i,
    const float* __restrict__ b_i,
    float* __restrict__ graph, __half* __restrict__ h2out)
{
    const int b = blockIdx.y;
    const int w = threadIdx.x >> 5, lane = threadIdx.x & 31;

    if (blockIdx.z == 0) {
        const int i = blockIdx.x;
        const float* xi = hijb + (size_t)(b * VV + i) * NCAT;
        float a[24];
        #pragma unroll
        for (int k = 0; k < 24; k++) {
            int idx = lane + 32*k;
            a[k] = xi[idx] + __ldg(bg1 + idx);
        }
        const float b20 = __ldg(bg2);
        float* orow = graph + (size_t)(b * VV + i) * VV;

        #pragma unroll 1
        for (int qj = 0; qj < 6; qj++) {
            const int j = w + 8*qj;
            const float* xj = hijb + (size_t)(b * VV + j) * NCAT + HH;
            float x[24];
            float s = 0.f, sq = 0.f;
            #pragma unroll
            for (int k = 0; k < 24; k++) {
                x[k] = a[k] + xj[lane + 32*k];
                s += x[k];
                sq = fmaf(x[k], x[k], sq);
            }
            #pragma unroll
            for (int o = 16; o > 0; o >>= 1) {
                s  += __shfl_xor_sync(0xffffffffu, s,  o);
                sq += __shfl_xor_sync(0xffffffffu, sq, o);
            }
            float mu = s * (1.f / HH);
            float var = sq * (1.f / HH) - mu * mu;
            float inv = rsqrtf(var + 1e-5f);
            float d = 0.f;
            #pragma unroll
            for (int k = 0; k < 24; k++) {
                int idx = lane + 32*k;
                float y = fmaxf((x[k] - mu) * inv * __ldg(g_g + idx) + __ldg(b_g + idx), 0.f);
                d = fmaf(y, __ldg(Wg2 + idx), d);
            }
            #pragma unroll
            for (int o = 16; o > 0; o >>= 1) d += __shfl_xor_sync(0xffffffffu, d, o);
            if (lane == 0)
                orow[j] = (i == j) ? 0.f : 1.f / (1.f + expf(-(d + b20)));
        }
    } else {
        const int i = blockIdx.x;
        if (i >= II) return;
        const float* xa = ha + (size_t)(b * II + i) * HH;
        float a[24];
        #pragma unroll
        for (int k = 0; k < 24; k++) {
            int idx = lane + 32*k;
            a[k] = xa[idx] + __ldg(bi1 + idx);
        }
        __half* yb = h2out + (size_t)(b * II + i) * VV * HH;

        #pragma unroll 1
        for (int qj = 0; qj < 6; qj++) {
            const int j = w + 8*qj;
            const float* xb = hijb + (size_t)(b * VV + j) * NCAT + 2 * HH;
            float x[24];
            float s = 0.f, sq = 0.f;
            #pragma unroll
            for (int k = 0; k < 24; k++) {
                x[k] = a[k] + xb[lane + 32*k];
                s += x[k];
                sq = fmaf(x[k], x[k], sq);
            }
            #pragma unroll
            for (int o = 16; o > 0; o >>= 1) {
                s  += __shfl_xor_sync(0xffffffffu, s,  o);
                sq += __shfl_xor_sync(0xffffffffu, sq, o);
            }
            float mu = s * (1.f / HH);
            float var = sq * (1.f / HH) - mu * mu;
            float inv = rsqrtf(var + 1e-5f);
            __half* y = yb + (size_t)j * HH;
            #pragma unroll
            for (int k = 0; k < 24; k++) {
                int idx = lane + 32*k;
                y[idx] = __float2half_rn(
                    fmaxf((x[k] - mu) * inv * __ldg(g_i + idx) + __ldg(b_i + idx), 0.f));
            }
        }
    }
}

extern "C" void kernel_launch(void* const* d_in, const int* in_sizes, int n_in,
                              void* d_out, int out_size) {
    const float* variables     = (const float*)d_in[0];
    const float* interventions = (const float*)d_in[1];
    const float* W_enc  = (const float*)d_in[2];
    const float* b_enc  = (const float*)d_in[3];
    const float* g_enc  = (const float*)d_in[4];
    const float* be_enc = (const float*)d_in[5];
    const float* Wg1    = (const float*)d_in[6];
    const float* bg1    = (const float*)d_in[7];
    const float* g_g    = (const float*)d_in[8];
    const float* b_g    = (const float*)d_in[9];
    const float* Wg2    = (const float*)d_in[10];
    const float* bg2    = (const float*)d_in[11];
    const float* Wi1    = (const float*)d_in[12];
    const float* bi1    = (const float*)d_in[13];
    const float* g_i    = (const float*)d_in[14];
    const float* b_i    = (const float*)d_in[15];
    const float* Wi2    = (const float*)d_in[16];
    const float* bi2    = (const float*)d_in[17];

    float* effects = (float*)d_out;
    float* graph   = effects + EFFECTS_ELEMS;
    float* enc     = graph + GRAPH_ELEMS;

    __half *p_varh, *p_Wench, *p_ench, *p_Bcath, *p_inth, *p_Wi1h, *p_Wi2h, *p_h2h;
    float *p_pre, *p_hijb, *p_ha;
    cudaGetSymbolAddress((void**)&p_varh,  g_varh);
    cudaGetSymbolAddress((void**)&p_Wench, g_Wench);
    cudaGetSymbolAddress((void**)&p_pre,   g_pre);
    cudaGetSymbolAddress((void**)&p_ench,  g_ench);
    cudaGetSymbolAddress((void**)&p_Bcath, g_Bcath);
    cudaGetSymbolAddress((void**)&p_hijb,  g_hijb);
    cudaGetSymbolAddress((void**)&p_inth,  g_inth);
    cudaGetSymbolAddress((void**)&p_Wi1h,  g_Wi1h);
    cudaGetSymbolAddress((void**)&p_ha,    g_ha);
    cudaGetSymbolAddress((void**)&p_Wi2h,  g_Wi2h);
    cudaGetSymbolAddress((void**)&p_h2h,   g_h2h);

    cudaFuncSetAttribute(hgemm_big,    cudaFuncAttributeMaxDynamicSharedMemorySize, HG_SMEM_BIG);
    cudaFuncSetAttribute(hgemm_sml,    cudaFuncAttributeMaxDynamicSharedMemorySize, HG_SMEM_SML);
    cudaFuncSetAttribute(hgemm_sml_b2, cudaFuncAttributeMaxDynamicSharedMemorySize, HG_SMEM_SML);

    dim3 blk(256);
    dim3 blk128(128);

    // 1) all converts in one vectorized launch
    prep_all<<<(PREP_TOTAL4 + 255)/256, blk>>>(
        variables, interventions, W_enc, Wi1, Wi2, Wg1,
        p_varh, p_inth, p_Wench, p_Wi1h, p_Wi2h, p_Bcath);

    // 2) pre + ha batched in one launch (216 CTAs, single pass)
    hgemm_sml_b2<<<dim3((M_ENC/64 + M_HA/64) * (HH/128)), blk128, HG_SMEM_SML>>>(
        p_varh, p_Wench, b_enc, p_pre, M_ENC/64,
        p_inth, p_Wi1h, nullptr, p_ha,
        HH, HH);

    // 3) enc = relu(LN(pre))
    ln_relu_kernel<<<M_ENC, blk>>>(p_pre, g_enc, be_enc, enc, p_ench);

    // 4) hijb = enc @ [Wg1a|Wg1b|Wi1b]  (432 CTAs, single pass)
    hgemm_sml<<<dim3(NCAT/128, M_ENC/64), blk128, HG_SMEM_SML>>>(
        p_ench, p_Bcath, nullptr, p_hijb, M_ENC, NCAT, HH);

    // 5) graph + h2 merged, warp-per-row, barrier-free
    pairwise_warp<<<dim3(VV, BB, 2), blk>>>(
        p_hijb, p_ha, bg1, g_g, b_g, Wg2, bg2, bi1, g_i, b_i, graph, p_h2h);

    // 6) effects = h2 @ Wi2 + bi2 (big tiles, 1728 CTAs)
    hgemm_big<<<dim3(HH/128, M_H2/128), blk, HG_SMEM_BIG>>>(
        p_h2h, p_Wi2h, bi2, effects, M_H2, HH, HH);
}